// round 1
// baseline (speedup 1.0000x reference)
#include <cuda_runtime.h>
#include <cstdint>

// GNN_9869834846215: two-layer cached GCN.
//   out = D^-1/2 A D^-1/2 ( relu( D^-1/2 A D^-1/2 (x W1) + b1 ) W2 ) + b2
// Restructured:  g = dinv ⊙ (h W);  s[dst] += g[src] over edges;
//                out = dinv ⊙ (s + g) + b    (self-loop folded in)
//
// N=100000, F=H=128, E=1.6M (read from in_sizes, clamped to NMAX).

#define NMAX 100000
#define FD 128

// Scratch (allocation-free rule: __device__ globals)
__device__ float d_dinv[NMAX];
__device__ float d_bufA[(size_t)NMAX * FD];  // g  (GEMM output, gather source)
__device__ float d_bufB[(size_t)NMAX * FD];  // s  (accumulator / elementwise)
__device__ int   d_is64;

// ---------------------------------------------------------------------------
// Detect whether edge_index is int64 or int32 (JAX x64-off canonicalizes to
// int32, but be robust). Values are node ids < 2^31, so int64 data has all
// high words == 0; int32 data interpreted as pairs has random high words.
__global__ void detect_kernel(const void* __restrict__ ei) {
    const int2* p = (const int2*)ei;
    int is64 = 1;
    for (int i = 0; i < 64; ++i)
        if (p[i].y != 0) { is64 = 0; break; }
    d_is64 = is64;
}

// deg starts at 1.0 (self loop)
__global__ void init_deg(int n) {
    int i = blockIdx.x * blockDim.x + threadIdx.x;
    if (i < n) d_dinv[i] = 1.0f;
}

__global__ void deg_count(const void* __restrict__ ei, int E) {
    int i = blockIdx.x * blockDim.x + threadIdx.x;
    if (i >= E) return;
    int d;
    if (d_is64) d = (int)((const long long*)ei)[(size_t)E + i];
    else        d = ((const int*)ei)[(size_t)E + i];
    atomicAdd(&d_dinv[d], 1.0f);
}

__global__ void finish_dinv(int n) {
    int i = blockIdx.x * blockDim.x + threadIdx.x;
    if (i < n) d_dinv[i] = rsqrtf(d_dinv[i]);  // deg >= 1 always (self loop)
}

__global__ void zero_buf(float* __restrict__ b, int n4) {
    int i = blockIdx.x * blockDim.x + threadIdx.x;
    if (i < n4) ((float4*)b)[i] = make_float4(0.f, 0.f, 0.f, 0.f);
}

// ---------------------------------------------------------------------------
// out[row] = dinv[row] * (in[row] @ W)      (in: [n,128], W: [128,128])
// Block: 512 threads, 128 rows/block, thread = (row_local, colgroup of 32).
// W staged in shared in two 64-row halves (stays under 48KB static smem).
__global__ void __launch_bounds__(512)
gemm_scale(const float* __restrict__ in, const float* __restrict__ W,
           float* __restrict__ out, int n) {
    __shared__ float Ws[64 * FD];
    const int tid = threadIdx.x;
    const int rl  = tid >> 2;
    const int cg  = tid & 3;
    const int row = blockIdx.x * 128 + rl;

    float acc[32];
#pragma unroll
    for (int c = 0; c < 32; ++c) acc[c] = 0.f;

    const float4* xr = (const float4*)(in + (size_t)(row < n ? row : 0) * FD);

#pragma unroll 1
    for (int half = 0; half < 2; ++half) {
        __syncthreads();
        {
            const float4* Wg  = (const float4*)(W + half * 64 * FD);
            float4*       Wsv = (float4*)Ws;
#pragma unroll
            for (int i = 0; i < 4; ++i) Wsv[tid + i * 512] = Wg[tid + i * 512];
        }
        __syncthreads();
        if (row < n) {
#pragma unroll 4
            for (int k4 = 0; k4 < 16; ++k4) {
                float4 xv = xr[half * 16 + k4];
                const float* w0 = &Ws[(k4 * 4 + 0) * FD + cg * 32];
                const float* w1 = w0 + FD;
                const float* w2 = w0 + 2 * FD;
                const float* w3 = w0 + 3 * FD;
#pragma unroll
                for (int c = 0; c < 32; ++c) acc[c] += xv.x * w0[c];
#pragma unroll
                for (int c = 0; c < 32; ++c) acc[c] += xv.y * w1[c];
#pragma unroll
                for (int c = 0; c < 32; ++c) acc[c] += xv.z * w2[c];
#pragma unroll
                for (int c = 0; c < 32; ++c) acc[c] += xv.w * w3[c];
            }
        }
    }

    if (row < n) {
        const float dv = d_dinv[row];
        float4* o = (float4*)(out + (size_t)row * FD + cg * 32);
#pragma unroll
        for (int q = 0; q < 8; ++q)
            o[q] = make_float4(acc[4 * q + 0] * dv, acc[4 * q + 1] * dv,
                               acc[4 * q + 2] * dv, acc[4 * q + 3] * dv);
    }
}

// ---------------------------------------------------------------------------
// One warp per edge: s[dst] += g[src] (128 floats = 32 lanes x float4,
// vectorized red.global.add.v4.f32 — 4x fewer atomic ops than scalar).
__global__ void aggregate(const void* __restrict__ ei, int E,
                          const float* __restrict__ g, float* __restrict__ s) {
    long long w = (long long)blockIdx.x * (blockDim.x >> 5) + (threadIdx.x >> 5);
    if (w >= E) return;
    const int lane = threadIdx.x & 31;

    int si, di;
    if (d_is64) {
        const long long* p = (const long long*)ei;
        si = (int)p[w];
        di = (int)p[(size_t)E + w];
    } else {
        const int* p = (const int*)ei;
        si = p[w];
        di = p[(size_t)E + w];
    }

    float4 v = __ldg((const float4*)(g + (size_t)si * FD + lane * 4));
    float* p = s + (size_t)di * FD + lane * 4;
    asm volatile("red.global.add.v4.f32 [%0], {%1,%2,%3,%4};"
                 :: "l"(p), "f"(v.x), "f"(v.y), "f"(v.z), "f"(v.w)
                 : "memory");
}

// ---------------------------------------------------------------------------
// out = dinv * (A + B) + bias   (optionally relu). float4-granular.
__global__ void epilogue(const float* __restrict__ A, const float* __restrict__ B,
                         const float* __restrict__ bias, float* __restrict__ out,
                         int n, int do_relu) {
    long long i = (long long)blockIdx.x * blockDim.x + threadIdx.x;
    if (i >= (long long)n * 32) return;
    const int row = (int)(i >> 5);
    const int c4  = (int)(i & 31);
    const float dv = d_dinv[row];
    float4 a  = ((const float4*)A)[i];
    float4 b  = ((const float4*)B)[i];
    float4 bs = ((const float4*)bias)[c4];
    float4 r;
    r.x = dv * (a.x + b.x) + bs.x;
    r.y = dv * (a.y + b.y) + bs.y;
    r.z = dv * (a.z + b.z) + bs.z;
    r.w = dv * (a.w + b.w) + bs.w;
    if (do_relu) {
        r.x = fmaxf(r.x, 0.f); r.y = fmaxf(r.y, 0.f);
        r.z = fmaxf(r.z, 0.f); r.w = fmaxf(r.w, 0.f);
    }
    ((float4*)out)[i] = r;
}

// ---------------------------------------------------------------------------
extern "C" void kernel_launch(void* const* d_in, const int* in_sizes, int n_in,
                              void* d_out, int out_size) {
    const float* x  = (const float*)d_in[0];
    const void*  ei = d_in[1];
    const float* W1 = (const float*)d_in[2];
    const float* b1 = (const float*)d_in[3];
    const float* W2 = (const float*)d_in[4];
    const float* b2 = (const float*)d_in[5];
    float* out = (float*)d_out;

    int n = in_sizes[0] / FD;
    if (n > NMAX) n = NMAX;
    const int E = in_sizes[1] / 2;

    float *bufA, *bufB;
    cudaGetSymbolAddress((void**)&bufA, d_bufA);
    cudaGetSymbolAddress((void**)&bufB, d_bufB);

    const int n4 = n * 32;  // float4 count per feature matrix

    detect_kernel<<<1, 1>>>(ei);
    init_deg<<<(n + 255) / 256, 256>>>(n);
    deg_count<<<(E + 255) / 256, 256>>>(ei, E);
    finish_dinv<<<(n + 255) / 256, 256>>>(n);

    // ---- layer 1 ----
    zero_buf<<<(n4 + 255) / 256, 256>>>(bufB, n4);
    gemm_scale<<<(n + 127) / 128, 512>>>(x, W1, bufA, n);
    aggregate<<<(E + 7) / 8, 256>>>(ei, E, bufA, bufB);
    // bufB <- relu(dinv*(bufB + bufA) + b1)   (in place)
    epilogue<<<(n4 + 255) / 256, 256>>>(bufA, bufB, b1, bufB, n, 1);

    // ---- layer 2 ----
    gemm_scale<<<(n + 127) / 128, 512>>>(bufB, W2, bufA, n);
    zero_buf<<<(n4 + 255) / 256, 256>>>(bufB, n4);
    aggregate<<<(E + 7) / 8, 256>>>(ei, E, bufA, bufB);
    epilogue<<<(n4 + 255) / 256, 256>>>(bufA, bufB, b2, out, n, 0);
}

// round 2
// speedup vs baseline: 1.3385x; 1.3385x over previous
#include <cuda_runtime.h>
#include <cstdint>

// GNN_9869834846215: two-layer cached GCN.
//   out = D^-1/2 A D^-1/2 ( relu( D^-1/2 A D^-1/2 (x W1) + b1 ) W2 ) + b2
// Restructured:  g = dinv ⊙ (h W);  s[dst] += g[src] over edges;
//                out = dinv ⊙ (s + g) + b    (self-loop folded in)
//
// N=100000, F=H=128, E=1.6M (read from in_sizes, clamped to NMAX).

#define NMAX 100000
#define FD 128

// Scratch (allocation-free rule: __device__ globals)
__device__ float d_dinv[NMAX];
__device__ float d_bufA[(size_t)NMAX * FD];  // g  (GEMM output, gather source)
__device__ float d_bufB[(size_t)NMAX * FD];  // s  (accumulator / elementwise)
__device__ int   d_is64;

// ---------------------------------------------------------------------------
// Detect whether edge_index is int64 or int32 (JAX x64-off canonicalizes to
// int32, but be robust). Values are node ids < 2^31, so int64 data has all
// high words == 0; int32 data interpreted as pairs has random high words.
__global__ void detect_kernel(const void* __restrict__ ei) {
    const int2* p = (const int2*)ei;
    int is64 = 1;
    for (int i = 0; i < 64; ++i)
        if (p[i].y != 0) { is64 = 0; break; }
    d_is64 = is64;
}

// deg starts at 1.0 (self loop)
__global__ void init_deg(int n) {
    int i = blockIdx.x * blockDim.x + threadIdx.x;
    if (i < n) d_dinv[i] = 1.0f;
}

__global__ void deg_count(const void* __restrict__ ei, int E) {
    int i = blockIdx.x * blockDim.x + threadIdx.x;
    if (i >= E) return;
    int d;
    if (d_is64) d = (int)((const long long*)ei)[(size_t)E + i];
    else        d = ((const int*)ei)[(size_t)E + i];
    atomicAdd(&d_dinv[d], 1.0f);
}

__global__ void finish_dinv(int n) {
    int i = blockIdx.x * blockDim.x + threadIdx.x;
    if (i < n) d_dinv[i] = rsqrtf(d_dinv[i]);  // deg >= 1 always (self loop)
}

__global__ void zero_buf(float* __restrict__ b, int n4) {
    int i = blockIdx.x * blockDim.x + threadIdx.x;
    if (i < n4) ((float4*)b)[i] = make_float4(0.f, 0.f, 0.f, 0.f);
}

// ---------------------------------------------------------------------------
// out[row] = dinv[row] * (in[row] @ W)      (in: [n,128], W: [128,128])
// Block: 512 threads, 128 rows/block, thread = (row_local, colgroup of 32).
// W staged in shared in two 64-row halves (stays under 48KB static smem).
__global__ void __launch_bounds__(512)
gemm_scale(const float* __restrict__ in, const float* __restrict__ W,
           float* __restrict__ out, int n) {
    __shared__ float Ws[64 * FD];
    const int tid = threadIdx.x;
    const int rl  = tid >> 2;
    const int cg  = tid & 3;
    const int row = blockIdx.x * 128 + rl;

    float acc[32];
#pragma unroll
    for (int c = 0; c < 32; ++c) acc[c] = 0.f;

    const float4* xr = (const float4*)(in + (size_t)(row < n ? row : 0) * FD);

#pragma unroll 1
    for (int half = 0; half < 2; ++half) {
        __syncthreads();
        {
            const float4* Wg  = (const float4*)(W + half * 64 * FD);
            float4*       Wsv = (float4*)Ws;
#pragma unroll
            for (int i = 0; i < 4; ++i) Wsv[tid + i * 512] = Wg[tid + i * 512];
        }
        __syncthreads();
        if (row < n) {
#pragma unroll 4
            for (int k4 = 0; k4 < 16; ++k4) {
                float4 xv = xr[half * 16 + k4];
                const float* w0 = &Ws[(k4 * 4 + 0) * FD + cg * 32];
                const float* w1 = w0 + FD;
                const float* w2 = w0 + 2 * FD;
                const float* w3 = w0 + 3 * FD;
#pragma unroll
                for (int c = 0; c < 32; ++c) acc[c] += xv.x * w0[c];
#pragma unroll
                for (int c = 0; c < 32; ++c) acc[c] += xv.y * w1[c];
#pragma unroll
                for (int c = 0; c < 32; ++c) acc[c] += xv.z * w2[c];
#pragma unroll
                for (int c = 0; c < 32; ++c) acc[c] += xv.w * w3[c];
            }
        }
    }

    if (row < n) {
        const float dv = d_dinv[row];
        float4* o = (float4*)(out + (size_t)row * FD + cg * 32);
#pragma unroll
        for (int q = 0; q < 8; ++q)
            o[q] = make_float4(acc[4 * q + 0] * dv, acc[4 * q + 1] * dv,
                               acc[4 * q + 2] * dv, acc[4 * q + 3] * dv);
    }
}

// ---------------------------------------------------------------------------
// One warp per edge: s[dst] += g[src] (128 floats = 32 lanes x float4,
// vectorized red.global.add.v4.f32 — 4x fewer atomic ops than scalar).
__global__ void aggregate(const void* __restrict__ ei, int E,
                          const float* __restrict__ g, float* __restrict__ s) {
    long long w = (long long)blockIdx.x * (blockDim.x >> 5) + (threadIdx.x >> 5);
    if (w >= E) return;
    const int lane = threadIdx.x & 31;

    int si, di;
    if (d_is64) {
        const long long* p = (const long long*)ei;
        si = (int)p[w];
        di = (int)p[(size_t)E + w];
    } else {
        const int* p = (const int*)ei;
        si = p[w];
        di = p[(size_t)E + w];
    }

    float4 v = __ldg((const float4*)(g + (size_t)si * FD + lane * 4));
    float* p = s + (size_t)di * FD + lane * 4;
    asm volatile("red.global.add.v4.f32 [%0], {%1,%2,%3,%4};"
                 :: "l"(p), "f"(v.x), "f"(v.y), "f"(v.z), "f"(v.w)
                 : "memory");
}

// ---------------------------------------------------------------------------
// out = dinv * (A + B) + bias   (optionally relu). float4-granular.
__global__ void epilogue(const float* __restrict__ A, const float* __restrict__ B,
                         const float* __restrict__ bias, float* __restrict__ out,
                         int n, int do_relu) {
    long long i = (long long)blockIdx.x * blockDim.x + threadIdx.x;
    if (i >= (long long)n * 32) return;
    const int row = (int)(i >> 5);
    const int c4  = (int)(i & 31);
    const float dv = d_dinv[row];
    float4 a  = ((const float4*)A)[i];
    float4 b  = ((const float4*)B)[i];
    float4 bs = ((const float4*)bias)[c4];
    float4 r;
    r.x = dv * (a.x + b.x) + bs.x;
    r.y = dv * (a.y + b.y) + bs.y;
    r.z = dv * (a.z + b.z) + bs.z;
    r.w = dv * (a.w + b.w) + bs.w;
    if (do_relu) {
        r.x = fmaxf(r.x, 0.f); r.y = fmaxf(r.y, 0.f);
        r.z = fmaxf(r.z, 0.f); r.w = fmaxf(r.w, 0.f);
    }
    ((float4*)out)[i] = r;
}

// ---------------------------------------------------------------------------
extern "C" void kernel_launch(void* const* d_in, const int* in_sizes, int n_in,
                              void* d_out, int out_size) {
    const float* x  = (const float*)d_in[0];
    const void*  ei = d_in[1];
    const float* W1 = (const float*)d_in[2];
    const float* b1 = (const float*)d_in[3];
    const float* W2 = (const float*)d_in[4];
    const float* b2 = (const float*)d_in[5];
    float* out = (float*)d_out;

    int n = in_sizes[0] / FD;
    if (n > NMAX) n = NMAX;
    const int E = in_sizes[1] / 2;

    float *bufA, *bufB;
    cudaGetSymbolAddress((void**)&bufA, d_bufA);
    cudaGetSymbolAddress((void**)&bufB, d_bufB);

    const int n4 = n * 32;  // float4 count per feature matrix

    detect_kernel<<<1, 1>>>(ei);
    init_deg<<<(n + 255) / 256, 256>>>(n);
    deg_count<<<(E + 255) / 256, 256>>>(ei, E);
    finish_dinv<<<(n + 255) / 256, 256>>>(n);

    // ---- layer 1 ----
    zero_buf<<<(n4 + 255) / 256, 256>>>(bufB, n4);
    gemm_scale<<<(n + 127) / 128, 512>>>(x, W1, bufA, n);
    aggregate<<<(E + 7) / 8, 256>>>(ei, E, bufA, bufB);
    // bufB <- relu(dinv*(bufB + bufA) + b1)   (in place)
    epilogue<<<(n4 + 255) / 256, 256>>>(bufA, bufB, b1, bufB, n, 1);

    // ---- layer 2 ----
    gemm_scale<<<(n + 127) / 128, 512>>>(bufB, W2, bufA, n);
    zero_buf<<<(n4 + 255) / 256, 256>>>(bufB, n4);
    aggregate<<<(E + 7) / 8, 256>>>(ei, E, bufA, bufB);
    epilogue<<<(n4 + 255) / 256, 256>>>(bufA, bufB, b2, out, n, 0);
}

// round 3
// speedup vs baseline: 1.5754x; 1.1770x over previous
#include <cuda_runtime.h>
#include <cstdint>

// GNN_9869834846215: two-layer cached GCN, CSR-gather formulation.
//   g = dinv ⊙ (h W)            (dense GEMM, dinv folded into output)
//   out[d] = dinv[d]*(Σ_{s in N(d)} g[s] + g[d]) + b   (warp-per-node gather)
// CSR (dst-sorted adjacency) built on-device each call; no feature atomics.

#define NMAX 100000
#define EMAX 1700000
#define FD 128
#define SCAN_T 1024
#define SCAN_C 4096          // elements per scan block (1024 threads x 4)
#define SCAN_NBLK ((NMAX + SCAN_C - 1) / SCAN_C)   // 25 (<=32 required)

// Scratch (__device__ globals per allocation-free rule)
__device__ float d_dinv[NMAX];
__device__ float d_bufA[(size_t)NMAX * FD];   // g (gather source)
__device__ float d_bufB[(size_t)NMAX * FD];   // h (hidden layer)
__device__ int   d_degi[NMAX];
__device__ int   d_off[NMAX + 1];
__device__ int   d_cursor[NMAX];
__device__ int   d_csr[EMAX];
__device__ int   d_blocksums[32];
__device__ int   d_is64;

// ---------------------------------------------------------------------------
// int64 vs int32 edge_index detection (JAX x64-off canonicalizes to int32).
__global__ void detect_kernel(const void* __restrict__ ei) {
    const int2* p = (const int2*)ei;
    int is64 = 1;
    for (int i = 0; i < 64; ++i)
        if (p[i].y != 0) { is64 = 0; break; }
    d_is64 = is64;
}

__device__ __forceinline__ int edge_at(const void* ei, size_t idx) {
    return d_is64 ? (int)((const long long*)ei)[idx] : ((const int*)ei)[idx];
}

__global__ void zero_deg(int n) {
    int i = blockIdx.x * blockDim.x + threadIdx.x;
    if (i < n) d_degi[i] = 0;
}

__global__ void deg_count(const void* __restrict__ ei, int E) {
    int i = blockIdx.x * blockDim.x + threadIdx.x;
    if (i >= E) return;
    atomicAdd(&d_degi[edge_at(ei, (size_t)E + i)], 1);
}

// ---------------------------------------------------------------------------
// Scan stage 1: per-chunk exclusive scan of deg, chunk totals to d_blocksums.
// Also computes dinv = rsqrt(deg+1) on the fly.
__global__ void __launch_bounds__(SCAN_T)
scan_partial(int n) {
    __shared__ int ssum[SCAN_T];
    const int tid  = threadIdx.x;
    const int base = blockIdx.x * SCAN_C + tid * 4;

    int v[4];
#pragma unroll
    for (int i = 0; i < 4; ++i) {
        v[i] = (base + i < n) ? d_degi[base + i] : 0;
        if (base + i < n) d_dinv[base + i] = rsqrtf((float)v[i] + 1.0f);
    }
    int tsum = v[0] + v[1] + v[2] + v[3];
    ssum[tid] = tsum;
    __syncthreads();
    // Hillis-Steele inclusive scan over 1024 thread sums
    for (int off = 1; off < SCAN_T; off <<= 1) {
        int t = (tid >= off) ? ssum[tid - off] : 0;
        __syncthreads();
        ssum[tid] += t;
        __syncthreads();
    }
    int texcl = ssum[tid] - tsum;
    if (tid == SCAN_T - 1) d_blocksums[blockIdx.x] = ssum[tid];

    int run = texcl;
#pragma unroll
    for (int i = 0; i < 4; ++i) {
        if (base + i < n) d_off[base + i] = run;
        run += v[i];
    }
}

// Scan stage 2: exclusive scan of <=32 chunk totals (single warp).
__global__ void scan_blocksums(int nblk) {
    int tid = threadIdx.x;
    int v = (tid < nblk) ? d_blocksums[tid] : 0;
    int orig = v;
#pragma unroll
    for (int o = 1; o < 32; o <<= 1) {
        int t = __shfl_up_sync(0xFFFFFFFFu, v, o);
        if (tid >= o) v += t;
    }
    if (tid < nblk) d_blocksums[tid] = v - orig;
}

// Scan stage 3: add chunk offsets; init cursor; set sentinel.
__global__ void scan_add(int n, int E) {
    int i = blockIdx.x * blockDim.x + threadIdx.x;
    if (i < n) {
        int v = d_off[i] + d_blocksums[i / SCAN_C];
        d_off[i] = v;
        d_cursor[i] = v;
    }
    if (i == 0) d_off[n] = E;
}

// Scatter src ids into CSR order (by dst).
__global__ void scatter_csr(const void* __restrict__ ei, int E) {
    int i = blockIdx.x * blockDim.x + threadIdx.x;
    if (i >= E) return;
    int si = edge_at(ei, i);
    int di = edge_at(ei, (size_t)E + i);
    int pos = atomicAdd(&d_cursor[di], 1);
    d_csr[pos] = si;
}

// ---------------------------------------------------------------------------
// out[row] = dinv[row] * (in[row] @ W)      (in: [n,128], W: [128,128])
__global__ void __launch_bounds__(512)
gemm_scale(const float* __restrict__ in, const float* __restrict__ W,
           float* __restrict__ out, int n) {
    __shared__ float Ws[64 * FD];
    const int tid = threadIdx.x;
    const int rl  = tid >> 2;
    const int cg  = tid & 3;
    const int row = blockIdx.x * 128 + rl;

    float acc[32];
#pragma unroll
    for (int c = 0; c < 32; ++c) acc[c] = 0.f;

    const float4* xr = (const float4*)(in + (size_t)(row < n ? row : 0) * FD);

#pragma unroll 1
    for (int half = 0; half < 2; ++half) {
        __syncthreads();
        {
            const float4* Wg  = (const float4*)(W + half * 64 * FD);
            float4*       Wsv = (float4*)Ws;
#pragma unroll
            for (int i = 0; i < 4; ++i) Wsv[tid + i * 512] = Wg[tid + i * 512];
        }
        __syncthreads();
        if (row < n) {
#pragma unroll 4
            for (int k4 = 0; k4 < 16; ++k4) {
                float4 xv = xr[half * 16 + k4];
                const float* w0 = &Ws[(k4 * 4 + 0) * FD + cg * 32];
                const float* w1 = w0 + FD;
                const float* w2 = w0 + 2 * FD;
                const float* w3 = w0 + 3 * FD;
#pragma unroll
                for (int c = 0; c < 32; ++c) acc[c] += xv.x * w0[c];
#pragma unroll
                for (int c = 0; c < 32; ++c) acc[c] += xv.y * w1[c];
#pragma unroll
                for (int c = 0; c < 32; ++c) acc[c] += xv.z * w2[c];
#pragma unroll
                for (int c = 0; c < 32; ++c) acc[c] += xv.w * w3[c];
            }
        }
    }

    if (row < n) {
        const float dv = d_dinv[row];
        float4* o = (float4*)(out + (size_t)row * FD + cg * 32);
#pragma unroll
        for (int q = 0; q < 8; ++q)
            o[q] = make_float4(acc[4 * q + 0] * dv, acc[4 * q + 1] * dv,
                               acc[4 * q + 2] * dv, acc[4 * q + 3] * dv);
    }
}

// ---------------------------------------------------------------------------
// Fused aggregate + epilogue: one warp per dst node.
//   out[d] = dinv[d] * (Σ_{s∈CSR(d)} g[s] + g[d]) + bias   [+relu]
__global__ void __launch_bounds__(256)
aggregate_csr(const float* __restrict__ g, const float* __restrict__ bias,
              float* __restrict__ out, int n, int do_relu) {
    const int w = blockIdx.x * 8 + (threadIdx.x >> 5);
    if (w >= n) return;
    const int lane = threadIdx.x & 31;

    const float4* gw = (const float4*)g + lane;   // lane's 16B column slice
    float4 acc = __ldg(gw + (size_t)w * 32);      // self-loop term

    int e = d_off[w];
    const int eend = d_off[w + 1];
    for (; e + 2 <= eend; e += 2) {
        int s0 = __ldg(&d_csr[e]);
        int s1 = __ldg(&d_csr[e + 1]);
        float4 a = __ldg(gw + (size_t)s0 * 32);
        float4 b = __ldg(gw + (size_t)s1 * 32);
        acc.x += a.x + b.x; acc.y += a.y + b.y;
        acc.z += a.z + b.z; acc.w += a.w + b.w;
    }
    if (e < eend) {
        int s0 = __ldg(&d_csr[e]);
        float4 a = __ldg(gw + (size_t)s0 * 32);
        acc.x += a.x; acc.y += a.y; acc.z += a.z; acc.w += a.w;
    }

    const float dv = d_dinv[w];
    float4 bs = __ldg((const float4*)bias + lane);
    float4 r;
    r.x = dv * acc.x + bs.x;
    r.y = dv * acc.y + bs.y;
    r.z = dv * acc.z + bs.z;
    r.w = dv * acc.w + bs.w;
    if (do_relu) {
        r.x = fmaxf(r.x, 0.f); r.y = fmaxf(r.y, 0.f);
        r.z = fmaxf(r.z, 0.f); r.w = fmaxf(r.w, 0.f);
    }
    ((float4*)(out + (size_t)w * FD))[lane] = r;
}

// ---------------------------------------------------------------------------
extern "C" void kernel_launch(void* const* d_in, const int* in_sizes, int n_in,
                              void* d_out, int out_size) {
    const float* x  = (const float*)d_in[0];
    const void*  ei = d_in[1];
    const float* W1 = (const float*)d_in[2];
    const float* b1 = (const float*)d_in[3];
    const float* W2 = (const float*)d_in[4];
    const float* b2 = (const float*)d_in[5];
    float* out = (float*)d_out;

    int n = in_sizes[0] / FD;
    if (n > NMAX) n = NMAX;
    int E = in_sizes[1] / 2;
    if (E > EMAX) E = EMAX;

    float *bufA, *bufB;
    cudaGetSymbolAddress((void**)&bufA, d_bufA);
    cudaGetSymbolAddress((void**)&bufB, d_bufB);

    const int nblk_scan = (n + SCAN_C - 1) / SCAN_C;

    // ---- CSR build (shared by both layers) ----
    detect_kernel<<<1, 1>>>(ei);
    zero_deg<<<(n + 255) / 256, 256>>>(n);
    deg_count<<<(E + 255) / 256, 256>>>(ei, E);
    scan_partial<<<nblk_scan, SCAN_T>>>(n);       // also computes dinv
    scan_blocksums<<<1, 32>>>(nblk_scan);
    scan_add<<<(n + 255) / 256, 256>>>(n, E);
    scatter_csr<<<(E + 255) / 256, 256>>>(ei, E);

    // ---- layer 1 ----
    gemm_scale<<<(n + 127) / 128, 512>>>(x, W1, bufA, n);
    aggregate_csr<<<(n + 7) / 8, 256>>>(bufA, b1, bufB, n, 1);

    // ---- layer 2 ----
    gemm_scale<<<(n + 127) / 128, 512>>>(bufB, W2, bufA, n);
    aggregate_csr<<<(n + 7) / 8, 256>>>(bufA, b2, out, n, 0);
}

// round 4
// speedup vs baseline: 8.3098x; 5.2747x over previous
#include <cuda_runtime.h>
#include <cstdint>

// GNN_9869834846215: two-layer cached GCN, CSR-gather formulation.
//   g = dinv ⊙ (h W)            (register-tiled GEMM, dinv folded into output)
//   out[d] = dinv[d]*(Σ_{s in N(d)} g[s] + g[d]) + b   (warp-per-node gather)

#define NMAX 100000
#define EMAX 1700000
#define FD 128
#define GSTRIDE 132              // padded smem row stride (16B-aligned, odd/4)
#define GEMM_SMEM (2 * 128 * GSTRIDE * 4)
#define SCAN_T 1024
#define SCAN_C 4096

// Scratch (__device__ globals per allocation-free rule)
__device__ float d_dinv[NMAX];
__device__ float d_bufA[(size_t)NMAX * FD];   // g (gather source)
__device__ float d_bufB[(size_t)NMAX * FD];   // h (hidden layer)
__device__ int   d_degi[NMAX];
__device__ int   d_off[NMAX + 1];
__device__ int   d_cursor[NMAX];
__device__ int   d_csr[EMAX];
__device__ int   d_blocksums[32];
__device__ int   d_is64;

// ---------------------------------------------------------------------------
// zero deg counters + (block 0, thread 0) int64-vs-int32 edge dtype detection
__global__ void zero_deg_detect(const void* __restrict__ ei, int n) {
    int i = blockIdx.x * blockDim.x + threadIdx.x;
    if (i < n) d_degi[i] = 0;
    if (blockIdx.x == 0 && threadIdx.x == 0) {
        const int2* p = (const int2*)ei;
        int is64 = 1;
        for (int j = 0; j < 64; ++j)
            if (p[j].y != 0) { is64 = 0; break; }
        d_is64 = is64;
    }
}

__device__ __forceinline__ int edge_at(const void* ei, size_t idx) {
    return d_is64 ? (int)((const long long*)ei)[idx] : ((const int*)ei)[idx];
}

__global__ void deg_count(const void* __restrict__ ei, int E) {
    int i = blockIdx.x * blockDim.x + threadIdx.x;
    if (i >= E) return;
    atomicAdd(&d_degi[edge_at(ei, (size_t)E + i)], 1);
}

__global__ void finish_dinv(int n) {
    int i = blockIdx.x * blockDim.x + threadIdx.x;
    if (i < n) d_dinv[i] = rsqrtf((float)d_degi[i] + 1.0f);
}

// ---------------------------------------------------------------------------
// GEMM: out[row] = dinv[row] * (in[row] @ W).  in:[n,128] W:[128,128].
// 256 threads, 128x128 tile, 8x8 regs/thread (rows {ty*4+i, 64+ty*4+i},
// cols {tx*4+j, 64+tx*4+j}).  Whole A-tile + W in dynamic smem (132KB).
__global__ void __launch_bounds__(256)
gemm_scale(const float* __restrict__ in, const float* __restrict__ W,
           float* __restrict__ out, int n) {
    extern __shared__ float smem[];
    float* As = smem;                    // [128][GSTRIDE]
    float* Ws = smem + 128 * GSTRIDE;    // [128][GSTRIDE]

    const int tid  = threadIdx.x;
    const int row0 = blockIdx.x * 128;

    // Load tiles: 4096 float4 each, coalesced 512B/warp.
#pragma unroll
    for (int i = 0; i < 16; ++i) {
        int idx = tid + i * 256;         // 0..4095
        int r   = idx >> 5;
        int c4  = idx & 31;
        int gr  = row0 + r;
        float4 v  = __ldg((const float4*)(in + (size_t)(gr < n ? gr : 0) * FD) + c4);
        *(float4*)&As[r * GSTRIDE + c4 * 4] = v;
        float4 wv = __ldg((const float4*)(W + (size_t)r * FD) + c4);
        *(float4*)&Ws[r * GSTRIDE + c4 * 4] = wv;
    }
    __syncthreads();

    const int ty = tid >> 4;   // 0..15
    const int tx = tid & 15;   // 0..15

    float acc[8][8];
#pragma unroll
    for (int i = 0; i < 8; ++i)
#pragma unroll
        for (int j = 0; j < 8; ++j) acc[i][j] = 0.f;

#pragma unroll 4
    for (int k = 0; k < 128; ++k) {
        float a[8];
#pragma unroll
        for (int i = 0; i < 4; ++i) {
            a[i]     = As[(ty * 4 + i) * GSTRIDE + k];        // 2-addr broadcast
            a[4 + i] = As[(64 + ty * 4 + i) * GSTRIDE + k];
        }
        float4 b0 = *(const float4*)&Ws[k * GSTRIDE + tx * 4];       // LDS.128
        float4 b1 = *(const float4*)&Ws[k * GSTRIDE + 64 + tx * 4];  // LDS.128
        float b[8] = {b0.x, b0.y, b0.z, b0.w, b1.x, b1.y, b1.z, b1.w};
#pragma unroll
        for (int i = 0; i < 8; ++i)
#pragma unroll
            for (int j = 0; j < 8; ++j) acc[i][j] += a[i] * b[j];
    }

#pragma unroll
    for (int i = 0; i < 8; ++i) {
        int rl = (i < 4) ? (ty * 4 + i) : (64 + ty * 4 + (i - 4));
        int r  = row0 + rl;
        if (r < n) {
            float dv = d_dinv[r];
            float4 o0 = make_float4(acc[i][0] * dv, acc[i][1] * dv,
                                    acc[i][2] * dv, acc[i][3] * dv);
            float4 o1 = make_float4(acc[i][4] * dv, acc[i][5] * dv,
                                    acc[i][6] * dv, acc[i][7] * dv);
            *(float4*)(out + (size_t)r * FD + tx * 4)      = o0;
            *(float4*)(out + (size_t)r * FD + 64 + tx * 4) = o1;
        }
    }
}

// ---------------------------------------------------------------------------
// Scan stage 1: per-chunk exclusive scan of deg, chunk totals to d_blocksums.
__global__ void __launch_bounds__(SCAN_T)
scan_partial(int n) {
    __shared__ int ssum[SCAN_T];
    const int tid  = threadIdx.x;
    const int base = blockIdx.x * SCAN_C + tid * 4;

    int v[4];
#pragma unroll
    for (int i = 0; i < 4; ++i)
        v[i] = (base + i < n) ? d_degi[base + i] : 0;
    int tsum = v[0] + v[1] + v[2] + v[3];
    ssum[tid] = tsum;
    __syncthreads();
    for (int off = 1; off < SCAN_T; off <<= 1) {
        int t = (tid >= off) ? ssum[tid - off] : 0;
        __syncthreads();
        ssum[tid] += t;
        __syncthreads();
    }
    int texcl = ssum[tid] - tsum;
    if (tid == SCAN_T - 1) d_blocksums[blockIdx.x] = ssum[tid];

    int run = texcl;
#pragma unroll
    for (int i = 0; i < 4; ++i) {
        if (base + i < n) d_off[base + i] = run;
        run += v[i];
    }
}

// Scan stage 2: exclusive scan of <=32 chunk totals (single warp).
__global__ void scan_blocksums(int nblk) {
    int tid = threadIdx.x;
    int v = (tid < nblk) ? d_blocksums[tid] : 0;
    int orig = v;
#pragma unroll
    for (int o = 1; o < 32; o <<= 1) {
        int t = __shfl_up_sync(0xFFFFFFFFu, v, o);
        if (tid >= o) v += t;
    }
    if (tid < nblk) d_blocksums[tid] = v - orig;
}

// Scan stage 3: add chunk offsets; init cursor; set sentinel.
__global__ void scan_add(int n, int E) {
    int i = blockIdx.x * blockDim.x + threadIdx.x;
    if (i < n) {
        int v = d_off[i] + d_blocksums[i / SCAN_C];
        d_off[i] = v;
        d_cursor[i] = v;
    }
    if (i == 0) d_off[n] = E;
}

// Scatter src ids into CSR order (by dst).
__global__ void scatter_csr(const void* __restrict__ ei, int E) {
    int i = blockIdx.x * blockDim.x + threadIdx.x;
    if (i >= E) return;
    int si = edge_at(ei, i);
    int di = edge_at(ei, (size_t)E + i);
    int pos = atomicAdd(&d_cursor[di], 1);
    d_csr[pos] = si;
}

// ---------------------------------------------------------------------------
// Fused aggregate + epilogue: one warp per dst node, 4 gathers in flight.
//   out[d] = dinv[d] * (Σ_{s∈CSR(d)} g[s] + g[d]) + bias   [+relu]
__global__ void __launch_bounds__(256)
aggregate_csr(const float* __restrict__ g, const float* __restrict__ bias,
              float* __restrict__ out, int n, int do_relu) {
    const int w = blockIdx.x * 8 + (threadIdx.x >> 5);
    if (w >= n) return;
    const int lane = threadIdx.x & 31;

    const float4* gw = (const float4*)g + lane;
    float4 acc = __ldg(gw + (size_t)w * 32);      // self-loop term

    int e = d_off[w];
    const int eend = d_off[w + 1];
    for (; e + 4 <= eend; e += 4) {
        int s0 = __ldg(&d_csr[e]);
        int s1 = __ldg(&d_csr[e + 1]);
        int s2 = __ldg(&d_csr[e + 2]);
        int s3 = __ldg(&d_csr[e + 3]);
        float4 a = __ldg(gw + (size_t)s0 * 32);
        float4 b = __ldg(gw + (size_t)s1 * 32);
        float4 c = __ldg(gw + (size_t)s2 * 32);
        float4 d = __ldg(gw + (size_t)s3 * 32);
        acc.x += (a.x + b.x) + (c.x + d.x);
        acc.y += (a.y + b.y) + (c.y + d.y);
        acc.z += (a.z + b.z) + (c.z + d.z);
        acc.w += (a.w + b.w) + (c.w + d.w);
    }
    for (; e < eend; ++e) {
        int s0 = __ldg(&d_csr[e]);
        float4 a = __ldg(gw + (size_t)s0 * 32);
        acc.x += a.x; acc.y += a.y; acc.z += a.z; acc.w += a.w;
    }

    const float dv = d_dinv[w];
    float4 bs = __ldg((const float4*)bias + lane);
    float4 r;
    r.x = dv * acc.x + bs.x;
    r.y = dv * acc.y + bs.y;
    r.z = dv * acc.z + bs.z;
    r.w = dv * acc.w + bs.w;
    if (do_relu) {
        r.x = fmaxf(r.x, 0.f); r.y = fmaxf(r.y, 0.f);
        r.z = fmaxf(r.z, 0.f); r.w = fmaxf(r.w, 0.f);
    }
    ((float4*)(out + (size_t)w * FD))[lane] = r;
}

// ---------------------------------------------------------------------------
extern "C" void kernel_launch(void* const* d_in, const int* in_sizes, int n_in,
                              void* d_out, int out_size) {
    const float* x  = (const float*)d_in[0];
    const void*  ei = d_in[1];
    const float* W1 = (const float*)d_in[2];
    const float* b1 = (const float*)d_in[3];
    const float* W2 = (const float*)d_in[4];
    const float* b2 = (const float*)d_in[5];
    float* out = (float*)d_out;

    int n = in_sizes[0] / FD;
    if (n > NMAX) n = NMAX;
    int E = in_sizes[1] / 2;
    if (E > EMAX) E = EMAX;

    float *bufA, *bufB;
    cudaGetSymbolAddress((void**)&bufA, d_bufA);
    cudaGetSymbolAddress((void**)&bufB, d_bufB);

    cudaFuncSetAttribute(gemm_scale,
                         cudaFuncAttributeMaxDynamicSharedMemorySize, GEMM_SMEM);

    const int nblk_scan = (n + SCAN_C - 1) / SCAN_C;
    const int gemm_grid = (n + 127) / 128;

    // launches 1-3: degree + dinv (gemm needs dinv; scan does not)
    zero_deg_detect<<<(n + 255) / 256, 256>>>(ei, n);
    deg_count<<<(E + 255) / 256, 256>>>(ei, E);
    finish_dinv<<<(n + 255) / 256, 256>>>(n);

    // launch 4 (ncu capture slot): layer-1 GEMM
    gemm_scale<<<gemm_grid, 256, GEMM_SMEM>>>(x, W1, bufA, n);

    // CSR build
    scan_partial<<<nblk_scan, SCAN_T>>>(n);
    scan_blocksums<<<1, 32>>>(nblk_scan);
    scan_add<<<(n + 255) / 256, 256>>>(n, E);
    scatter_csr<<<(E + 255) / 256, 256>>>(ei, E);

    // layer 1 aggregate (+relu)
    aggregate_csr<<<(n + 7) / 8, 256>>>(bufA, b1, bufB, n, 1);

    // layer 2
    gemm_scale<<<gemm_grid, 256, GEMM_SMEM>>>(bufB, W2, bufA, n);
    aggregate_csr<<<(n + 7) / 8, 256>>>(bufA, b2, out, n, 0);
}

// round 6
// speedup vs baseline: 10.1160x; 1.2174x over previous
#include <cuda_runtime.h>
#include <cuda_bf16.h>
#include <cstdint>

// GNN_9869834846215: two-layer cached GCN.
//   g = dinv ⊙ (h W)  -- HMMA (mma.sync bf16x2-split, fp32 acc) GEMM
//   out[d] = dinv[d]*(Σ_{s∈N(d)} g[s] + g[d]) + b  -- CSR warp-per-node gather

#define NMAX 100000
#define EMAX 1700000
#define FD 128
#define SCAN_T 1024
#define SCAN_C 4096

#define BSTRIDE 136                       // bf16 row stride (272B): ldmatrix conflict-free
#define TILE_SH (128 * BSTRIDE * 2)       // 34816 B per bf16 tile
#define GEMM_SMEM (4 * TILE_SH)           // Ah, Al, Bh, Bl

// Scratch (__device__ globals per allocation-free rule)
__device__ float d_dinv[NMAX];
__device__ float d_bufA[(size_t)NMAX * FD];
__device__ float d_bufB[(size_t)NMAX * FD];
__device__ int   d_degi[NMAX];
__device__ int   d_off[NMAX + 1];
__device__ int   d_cursor[NMAX];
__device__ int   d_csr[EMAX];
__device__ int   d_blocksums[32];
__device__ int   d_is64;
// W^T split into bf16 hi/lo, layout [n][k] with row stride BSTRIDE
__device__ __align__(16) unsigned short d_Whi[128 * BSTRIDE];
__device__ __align__(16) unsigned short d_Wlo[128 * BSTRIDE];

// ---------------------------------------------------------------------------
__device__ __forceinline__ uint32_t smem_u32(const void* p) {
    uint32_t a;
    asm("{ .reg .u64 t; cvta.to.shared.u64 t, %1; cvt.u32.u64 %0, t; }"
        : "=r"(a) : "l"(p));
    return a;
}

__device__ __forceinline__ void ldm_x4(uint32_t* r, uint32_t addr) {
    asm volatile("ldmatrix.sync.aligned.m8n8.x4.shared.b16 {%0,%1,%2,%3}, [%4];"
                 : "=r"(r[0]), "=r"(r[1]), "=r"(r[2]), "=r"(r[3]) : "r"(addr));
}

__device__ __forceinline__ void mma_bf16(float* c, const uint32_t* a,
                                         const uint32_t* b) {
    asm volatile(
        "mma.sync.aligned.m16n8k16.row.col.f32.bf16.bf16.f32 "
        "{%0,%1,%2,%3}, {%4,%5,%6,%7}, {%8,%9}, {%0,%1,%2,%3};"
        : "+f"(c[0]), "+f"(c[1]), "+f"(c[2]), "+f"(c[3])
        : "r"(a[0]), "r"(a[1]), "r"(a[2]), "r"(a[3]), "r"(b[0]), "r"(b[1]));
}

__device__ __forceinline__ unsigned short bfbits(__nv_bfloat16 h) {
    return __bfloat16_as_ushort(h);
}

// ---------------------------------------------------------------------------
// Split one W element into the hi/lo B images. B[n][k] = W[k][n].
__device__ __forceinline__ void w_split_elem(const float* W, int idx) {
    int nn = idx & 127, kk = idx >> 7;
    float v = W[kk * FD + nn];
    __nv_bfloat16 hi = __float2bfloat16_rn(v);
    __nv_bfloat16 lo = __float2bfloat16_rn(v - __bfloat162float(hi));
    d_Whi[nn * BSTRIDE + kk] = bfbits(hi);
    d_Wlo[nn * BSTRIDE + kk] = bfbits(lo);
}

__global__ void w_split(const float* __restrict__ W) {
    int idx = blockIdx.x * 256 + threadIdx.x;
    if (idx < 16384) w_split_elem(W, idx);
}

// zero deg counters + edge dtype detect + W1 split
__global__ void zero_deg_detect(const void* __restrict__ ei,
                                const float* __restrict__ W1, int n) {
    int i = blockIdx.x * blockDim.x + threadIdx.x;
    if (i < n) d_degi[i] = 0;
    if (i < 16384) w_split_elem(W1, i);
    if (i == 0) {
        const int2* p = (const int2*)ei;
        int is64 = 1;
        for (int j = 0; j < 64; ++j)
            if (p[j].y != 0) { is64 = 0; break; }
        d_is64 = is64;
    }
}

__device__ __forceinline__ int edge_at(const void* ei, size_t idx) {
    return d_is64 ? (int)((const long long*)ei)[idx] : ((const int*)ei)[idx];
}

__global__ void deg_count(const void* __restrict__ ei, int E) {
    int i = blockIdx.x * blockDim.x + threadIdx.x;
    if (i >= E) return;
    atomicAdd(&d_degi[edge_at(ei, (size_t)E + i)], 1);
}

__global__ void finish_dinv(int n) {
    int i = blockIdx.x * blockDim.x + threadIdx.x;
    if (i < n) d_dinv[i] = rsqrtf((float)d_degi[i] + 1.0f);
}

// ---------------------------------------------------------------------------
// HMMA GEMM: out[row] = dinv[row] * (in[row] @ W), W images in d_Whi/d_Wlo.
// 128x128 tile/block, 8 warps, warp tile 64x32, bf16 hi/lo split (3 terms).
__global__ void __launch_bounds__(256)
gemm_tc(const float* __restrict__ in, float* __restrict__ out, int n) {
    extern __shared__ char dsm[];
    char* sAh = dsm;
    char* sAl = dsm + TILE_SH;
    char* sBh = dsm + 2 * TILE_SH;
    char* sBl = dsm + 3 * TILE_SH;

    const int tid = threadIdx.x;
    const int wid = tid >> 5;
    const int lid = tid & 31;
    const int row0 = blockIdx.x * 128;

    // --- Stage B: linear copy of pre-split global images (incl. padding) ---
    {
        const float4* wh = (const float4*)d_Whi;
        const float4* wl = (const float4*)d_Wlo;
        float4* bh = (float4*)sBh;
        float4* bl = (float4*)sBl;
        for (int i = tid; i < TILE_SH / 16; i += 256) { bh[i] = wh[i]; bl[i] = wl[i]; }
    }
    // --- Stage A: load fp32, split hi/lo bf16 ---
    {
        int r = tid >> 1, h = tid & 1;
        int gr = row0 + r;
        if (gr >= n) gr = n - 1;
        const float4* src = (const float4*)(in + (size_t)gr * FD) + h * 16;
        unsigned short* ah = (unsigned short*)sAh + r * BSTRIDE;
        unsigned short* al = (unsigned short*)sAl + r * BSTRIDE;
#pragma unroll
        for (int i = 0; i < 16; ++i) {
            float4 v = __ldg(src + i);
            int k = h * 64 + i * 4;
            __nv_bfloat16 h0 = __float2bfloat16_rn(v.x);
            __nv_bfloat16 h1 = __float2bfloat16_rn(v.y);
            __nv_bfloat16 h2 = __float2bfloat16_rn(v.z);
            __nv_bfloat16 h3 = __float2bfloat16_rn(v.w);
            uint32_t hiA = (uint32_t)bfbits(h0) | ((uint32_t)bfbits(h1) << 16);
            uint32_t hiB = (uint32_t)bfbits(h2) | ((uint32_t)bfbits(h3) << 16);
            uint32_t loA = (uint32_t)bfbits(__float2bfloat16_rn(v.x - __bfloat162float(h0))) |
                           ((uint32_t)bfbits(__float2bfloat16_rn(v.y - __bfloat162float(h1))) << 16);
            uint32_t loB = (uint32_t)bfbits(__float2bfloat16_rn(v.z - __bfloat162float(h2))) |
                           ((uint32_t)bfbits(__float2bfloat16_rn(v.w - __bfloat162float(h3))) << 16);
            *(uint32_t*)(ah + k)     = hiA;
            *(uint32_t*)(ah + k + 2) = hiB;
            *(uint32_t*)(al + k)     = loA;
            *(uint32_t*)(al + k + 2) = loB;
        }
    }
    __syncthreads();

    // --- Warp tiling: warp (wid/4) -> M half, (wid%4) -> N quarter ---
    const int mrow0 = (wid >> 2) * 64;     // 0 or 64
    const int ncol0 = (wid & 3) * 32;      // 0,32,64,96

    // ldmatrix per-lane address offsets (bytes)
    const int sel   = lid >> 3;            // matrix index 0..3
    const int rowIn = lid & 7;
    // A x4: matrices (r0-7,kLo),(r8-15,kLo),(r0-7,kHi),(r8-15,kHi)
    const uint32_t aoff =
        (uint32_t)(((mrow0 + rowIn + (sel & 1) * 8) * BSTRIDE + (sel >> 1) * 8) * 2);
    // B x4: matrices (nEven,kLo),(nEven,kHi),(nOdd,kLo),(nOdd,kHi)
    const uint32_t boff =
        (uint32_t)(((ncol0 + (sel >> 1) * 8 + rowIn) * BSTRIDE + (sel & 1) * 8) * 2);

    const uint32_t aHi = smem_u32(sAh) + aoff;
    const uint32_t aLo = smem_u32(sAl) + aoff;
    const uint32_t bHi = smem_u32(sBh) + boff;
    const uint32_t bLo = smem_u32(sBl) + boff;

    float acc[4][4][4];
#pragma unroll
    for (int i = 0; i < 4; ++i)
#pragma unroll
        for (int j = 0; j < 4; ++j)
#pragma unroll
            for (int q = 0; q < 4; ++q) acc[i][j][q] = 0.f;

#pragma unroll
    for (int ks = 0; ks < 8; ++ks) {
        const uint32_t kb = ks * 32;       // k0*2 bytes (k0 = 16*ks)
        uint32_t ah[4][4], al[4][4], bh[4][2], bl[4][2];
#pragma unroll
        for (int i = 0; i < 4; ++i) {
            ldm_x4(ah[i], aHi + i * (16 * BSTRIDE * 2) + kb);
            ldm_x4(al[i], aLo + i * (16 * BSTRIDE * 2) + kb);
        }
#pragma unroll
        for (int j2 = 0; j2 < 2; ++j2) {
            uint32_t q[4];
            ldm_x4(q, bHi + j2 * (16 * BSTRIDE * 2) + kb);
            bh[2 * j2][0] = q[0]; bh[2 * j2][1] = q[1];
            bh[2 * j2 + 1][0] = q[2]; bh[2 * j2 + 1][1] = q[3];
            ldm_x4(q, bLo + j2 * (16 * BSTRIDE * 2) + kb);
            bl[2 * j2][0] = q[0]; bl[2 * j2][1] = q[1];
            bl[2 * j2 + 1][0] = q[2]; bl[2 * j2 + 1][1] = q[3];
        }
#pragma unroll
        for (int i = 0; i < 4; ++i)
#pragma unroll
            for (int j = 0; j < 4; ++j) {
                mma_bf16(acc[i][j], ah[i], bh[j]);
                mma_bf16(acc[i][j], ah[i], bl[j]);
                mma_bf16(acc[i][j], al[i], bh[j]);
            }
    }

    // --- Epilogue: scale by dinv, store fp32 ---
    const int rbase = row0 + mrow0 + (lid >> 2);
    const int cbase = ncol0 + 2 * (lid & 3);
#pragma unroll
    for (int i = 0; i < 4; ++i) {
        int r1 = rbase + 16 * i;
        int r2 = r1 + 8;
        float dv1 = (r1 < n) ? d_dinv[r1] : 0.f;
        float dv2 = (r2 < n) ? d_dinv[r2] : 0.f;
#pragma unroll
        for (int j = 0; j < 4; ++j) {
            int c = cbase + 8 * j;
            if (r1 < n)
                *(float2*)(out + (size_t)r1 * FD + c) =
                    make_float2(acc[i][j][0] * dv1, acc[i][j][1] * dv1);
            if (r2 < n)
                *(float2*)(out + (size_t)r2 * FD + c) =
                    make_float2(acc[i][j][2] * dv2, acc[i][j][3] * dv2);
        }
    }
}

// ---------------------------------------------------------------------------
// CSR build: chunked exclusive scan of in-degrees.
__global__ void __launch_bounds__(SCAN_T)
scan_partial(int n) {
    __shared__ int ssum[SCAN_T];
    const int tid  = threadIdx.x;
    const int base = blockIdx.x * SCAN_C + tid * 4;

    int v[4];
#pragma unroll
    for (int i = 0; i < 4; ++i)
        v[i] = (base + i < n) ? d_degi[base + i] : 0;
    int tsum = v[0] + v[1] + v[2] + v[3];
    ssum[tid] = tsum;
    __syncthreads();
    for (int off = 1; off < SCAN_T; off <<= 1) {
        int t = (tid >= off) ? ssum[tid - off] : 0;
        __syncthreads();
        ssum[tid] += t;
        __syncthreads();
    }
    int texcl = ssum[tid] - tsum;
    if (tid == SCAN_T - 1) d_blocksums[blockIdx.x] = ssum[tid];

    int run = texcl;
#pragma unroll
    for (int i = 0; i < 4; ++i) {
        if (base + i < n) d_off[base + i] = run;
        run += v[i];
    }
}

__global__ void scan_blocksums(int nblk) {
    int tid = threadIdx.x;
    int v = (tid < nblk) ? d_blocksums[tid] : 0;
    int orig = v;
#pragma unroll
    for (int o = 1; o < 32; o <<= 1) {
        int t = __shfl_up_sync(0xFFFFFFFFu, v, o);
        if (tid >= o) v += t;
    }
    if (tid < nblk) d_blocksums[tid] = v - orig;
}

__global__ void scan_add(int n, int E) {
    int i = blockIdx.x * blockDim.x + threadIdx.x;
    if (i < n) {
        int v = d_off[i] + d_blocksums[i / SCAN_C];
        d_off[i] = v;
        d_cursor[i] = v;
    }
    if (i == 0) d_off[n] = E;
}

__global__ void scatter_csr(const void* __restrict__ ei, int E) {
    int i = blockIdx.x * blockDim.x + threadIdx.x;
    if (i >= E) return;
    int si = edge_at(ei, i);
    int di = edge_at(ei, (size_t)E + i);
    int pos = atomicAdd(&d_cursor[di], 1);
    d_csr[pos] = si;
}

// ---------------------------------------------------------------------------
// Fused aggregate + epilogue: one warp per dst node, 4 gathers in flight.
__global__ void __launch_bounds__(256)
aggregate_csr(const float* __restrict__ g, const float* __restrict__ bias,
              float* __restrict__ out, int n, int do_relu) {
    const int w = blockIdx.x * 8 + (threadIdx.x >> 5);
    if (w >= n) return;
    const int lane = threadIdx.x & 31;

    const float4* gw = (const float4*)g + lane;
    float4 acc = __ldg(gw + (size_t)w * 32);      // self-loop term

    int e = d_off[w];
    const int eend = d_off[w + 1];
    for (; e + 4 <= eend; e += 4) {
        int s0 = __ldg(&d_csr[e]);
        int s1 = __ldg(&d_csr[e + 1]);
        int s2 = __ldg(&d_csr[e + 2]);
        int s3 = __ldg(&d_csr[e + 3]);
        float4 a = __ldg(gw + (size_t)s0 * 32);
        float4 b = __ldg(gw + (size_t)s1 * 32);
        float4 c = __ldg(gw + (size_t)s2 * 32);
        float4 d = __ldg(gw + (size_t)s3 * 32);
        acc.x += (a.x + b.x) + (c.x + d.x);
        acc.y += (a.y + b.y) + (c.y + d.y);
        acc.z += (a.z + b.z) + (c.z + d.z);
        acc.w += (a.w + b.w) + (c.w + d.w);
    }
    for (; e < eend; ++e) {
        int s0 = __ldg(&d_csr[e]);
        float4 a = __ldg(gw + (size_t)s0 * 32);
        acc.x += a.x; acc.y += a.y; acc.z += a.z; acc.w += a.w;
    }

    const float dv = d_dinv[w];
    float4 bs = __ldg((const float4*)bias + lane);
    float4 r;
    r.x = dv * acc.x + bs.x;
    r.y = dv * acc.y + bs.y;
    r.z = dv * acc.z + bs.z;
    r.w = dv * acc.w + bs.w;
    if (do_relu) {
        r.x = fmaxf(r.x, 0.f); r.y = fmaxf(r.y, 0.f);
        r.z = fmaxf(r.z, 0.f); r.w = fmaxf(r.w, 0.f);
    }
    ((float4*)(out + (size_t)w * FD))[lane] = r;
}

// ---------------------------------------------------------------------------
extern "C" void kernel_launch(void* const* d_in, const int* in_sizes, int n_in,
                              void* d_out, int out_size) {
    const float* x  = (const float*)d_in[0];
    const void*  ei = d_in[1];
    const float* W1 = (const float*)d_in[2];
    const float* b1 = (const float*)d_in[3];
    const float* W2 = (const float*)d_in[4];
    const float* b2 = (const float*)d_in[5];
    float* out = (float*)d_out;

    int n = in_sizes[0] / FD;
    if (n > NMAX) n = NMAX;
    int E = in_sizes[1] / 2;
    if (E > EMAX) E = EMAX;

    float *bufA, *bufB;
    cudaGetSymbolAddress((void**)&bufA, d_bufA);
    cudaGetSymbolAddress((void**)&bufB, d_bufB);

    cudaFuncSetAttribute(gemm_tc,
                         cudaFuncAttributeMaxDynamicSharedMemorySize, GEMM_SMEM);

    const int nblk_scan = (n + SCAN_C - 1) / SCAN_C;
    const int gemm_grid = (n + 127) / 128;

    // 1-3: degree + dinv + W1 split
    zero_deg_detect<<<(n + 255) / 256, 256>>>(ei, W1, n);
    deg_count<<<(E + 255) / 256, 256>>>(ei, E);
    finish_dinv<<<(n + 255) / 256, 256>>>(n);

    // 4 (ncu capture slot): layer-1 HMMA GEMM
    gemm_tc<<<gemm_grid, 256, GEMM_SMEM>>>(x, bufA, n);

    // 5: split W2 into the (now free) W image buffers
    w_split<<<64, 256>>>(W2);

    // CSR build
    scan_partial<<<nblk_scan, SCAN_T>>>(n);
    scan_blocksums<<<1, 32>>>(nblk_scan);
    scan_add<<<(n + 255) / 256, 256>>>(n, E);
    scatter_csr<<<(E + 255) / 256, 256>>>(ei, E);

    // layer 1 aggregate (+relu)
    aggregate_csr<<<(n + 7) / 8, 256>>>(bufA, b1, bufB, n, 1);

    // layer 2
    gemm_tc<<<gemm_grid, 256, GEMM_SMEM>>>(bufB, bufA, n);
    aggregate_csr<<<(n + 7) / 8, 256>>>(bufA, b2, out, n, 0);
}

// round 7
// speedup vs baseline: 10.4327x; 1.0313x over previous
#include <cuda_runtime.h>
#include <cuda_bf16.h>
#include <cuda_fp16.h>
#include <cstdint>

// GNN_9869834846215: two-layer cached GCN.
//   g = dinv ⊙ (h W)  -- HMMA bf16x2-split GEMM, fp16 output (gather source)
//   out[d] = dinv[d]*(Σ_{s∈N(d)} g[s] + g[d]) + b  -- CSR warp-per-node gather

#define NMAX 100000
#define EMAX 1700000
#define FD 128
#define SCAN_T 1024
#define SCAN_C 4096

#define BSTRIDE 136                       // bf16 row stride (272B): ldmatrix conflict-free
#define A_SH (64 * BSTRIDE * 2)           // 17408 B (64-row A tile, bf16)
#define B_SH (128 * BSTRIDE * 2)          // 34816 B (full W tile, bf16)
#define GEMM_SMEM (2 * A_SH + 2 * B_SH)   // 104448 B -> 2 blocks/SM

// Scratch (__device__ globals per allocation-free rule)
__device__ float d_dinv[NMAX];
__device__ float d_bufA[(size_t)NMAX * FD];   // g (fp16, viewed as half*)
__device__ float d_bufB[(size_t)NMAX * FD];   // h (fp32)
__device__ int   d_degi[NMAX];
__device__ int   d_off[NMAX + 1];
__device__ int   d_cursor[NMAX];
__device__ int   d_csr[EMAX];
__device__ int   d_blocksums[32];
__device__ int   d_is64;
// W^T split into bf16 hi/lo, layout [n][k] with row stride BSTRIDE
__device__ __align__(16) unsigned short d_Whi[128 * BSTRIDE];
__device__ __align__(16) unsigned short d_Wlo[128 * BSTRIDE];

// ---------------------------------------------------------------------------
__device__ __forceinline__ uint32_t smem_u32(const void* p) {
    uint32_t a;
    asm("{ .reg .u64 t; cvta.to.shared.u64 t, %1; cvt.u32.u64 %0, t; }"
        : "=r"(a) : "l"(p));
    return a;
}

__device__ __forceinline__ void ldm_x4(uint32_t* r, uint32_t addr) {
    asm volatile("ldmatrix.sync.aligned.m8n8.x4.shared.b16 {%0,%1,%2,%3}, [%4];"
                 : "=r"(r[0]), "=r"(r[1]), "=r"(r[2]), "=r"(r[3]) : "r"(addr));
}

__device__ __forceinline__ void mma_bf16(float* c, const uint32_t* a,
                                         const uint32_t* b) {
    asm volatile(
        "mma.sync.aligned.m16n8k16.row.col.f32.bf16.bf16.f32 "
        "{%0,%1,%2,%3}, {%4,%5,%6,%7}, {%8,%9}, {%0,%1,%2,%3};"
        : "+f"(c[0]), "+f"(c[1]), "+f"(c[2]), "+f"(c[3])
        : "r"(a[0]), "r"(a[1]), "r"(a[2]), "r"(a[3]), "r"(b[0]), "r"(b[1]));
}

__device__ __forceinline__ unsigned short bfbits(__nv_bfloat16 h) {
    return __bfloat16_as_ushort(h);
}

// ---------------------------------------------------------------------------
// Split one W element into the hi/lo B images. B[n][k] = W[k][n].
__device__ __forceinline__ void w_split_elem(const float* W, int idx) {
    int nn = idx & 127, kk = idx >> 7;
    float v = W[kk * FD + nn];
    __nv_bfloat16 hi = __float2bfloat16_rn(v);
    __nv_bfloat16 lo = __float2bfloat16_rn(v - __bfloat162float(hi));
    d_Whi[nn * BSTRIDE + kk] = bfbits(hi);
    d_Wlo[nn * BSTRIDE + kk] = bfbits(lo);
}

__global__ void w_split(const float* __restrict__ W) {
    int idx = blockIdx.x * 256 + threadIdx.x;
    if (idx < 16384) w_split_elem(W, idx);
}

// zero deg counters + edge dtype detect + W1 split
__global__ void zero_deg_detect(const void* __restrict__ ei,
                                const float* __restrict__ W1, int n) {
    int i = blockIdx.x * blockDim.x + threadIdx.x;
    if (i < n) d_degi[i] = 0;
    if (i < 16384) w_split_elem(W1, i);
    if (i == 0) {
        const int2* p = (const int2*)ei;
        int is64 = 1;
        for (int j = 0; j < 64; ++j)
            if (p[j].y != 0) { is64 = 0; break; }
        d_is64 = is64;
    }
}

__device__ __forceinline__ int edge_at(const void* ei, size_t idx) {
    return d_is64 ? (int)((const long long*)ei)[idx] : ((const int*)ei)[idx];
}

__global__ void deg_count(const void* __restrict__ ei, int E) {
    int i = blockIdx.x * blockDim.x + threadIdx.x;
    if (i >= E) return;
    atomicAdd(&d_degi[edge_at(ei, (size_t)E + i)], 1);
}

__global__ void finish_dinv(int n) {
    int i = blockIdx.x * blockDim.x + threadIdx.x;
    if (i < n) d_dinv[i] = rsqrtf((float)d_degi[i] + 1.0f);
}

// ---------------------------------------------------------------------------
// HMMA GEMM: gout[row] = fp16( dinv[row] * (in[row] @ W) ).
// 64-row tile / 128-thread block (104.4KB smem -> 2 blocks/SM for overlap).
// Warp tile: 16 rows x 128 cols; bf16 hi/lo split, 3 MMA terms, fp32 acc.
__global__ void __launch_bounds__(128)
gemm_tc(const float* __restrict__ in, __half* __restrict__ gout, int n) {
    extern __shared__ char dsm[];
    char* sAh = dsm;
    char* sAl = dsm + A_SH;
    char* sBh = dsm + 2 * A_SH;
    char* sBl = dsm + 2 * A_SH + B_SH;

    const int tid = threadIdx.x;
    const int wid = tid >> 5;
    const int lid = tid & 31;
    const int row0 = blockIdx.x * 64;

    // --- Stage B: linear copy of pre-split global images ---
    {
        const float4* wh = (const float4*)d_Whi;
        const float4* wl = (const float4*)d_Wlo;
        float4* bh = (float4*)sBh;
        float4* bl = (float4*)sBl;
        for (int i = tid; i < B_SH / 16; i += 128) { bh[i] = wh[i]; bl[i] = wl[i]; }
    }
    // --- Stage A: load fp32, split hi/lo bf16 ---
    {
        int r = tid >> 1, h = tid & 1;
        int gr = row0 + r;
        if (gr >= n) gr = n - 1;
        const float4* src = (const float4*)(in + (size_t)gr * FD) + h * 16;
        unsigned short* ah = (unsigned short*)sAh + r * BSTRIDE;
        unsigned short* al = (unsigned short*)sAl + r * BSTRIDE;
#pragma unroll
        for (int i = 0; i < 16; ++i) {
            float4 v = __ldg(src + i);
            int k = h * 64 + i * 4;
            __nv_bfloat16 h0 = __float2bfloat16_rn(v.x);
            __nv_bfloat16 h1 = __float2bfloat16_rn(v.y);
            __nv_bfloat16 h2 = __float2bfloat16_rn(v.z);
            __nv_bfloat16 h3 = __float2bfloat16_rn(v.w);
            uint32_t hiA = (uint32_t)bfbits(h0) | ((uint32_t)bfbits(h1) << 16);
            uint32_t hiB = (uint32_t)bfbits(h2) | ((uint32_t)bfbits(h3) << 16);
            uint32_t loA = (uint32_t)bfbits(__float2bfloat16_rn(v.x - __bfloat162float(h0))) |
                           ((uint32_t)bfbits(__float2bfloat16_rn(v.y - __bfloat162float(h1))) << 16);
            uint32_t loB = (uint32_t)bfbits(__float2bfloat16_rn(v.z - __bfloat162float(h2))) |
                           ((uint32_t)bfbits(__float2bfloat16_rn(v.w - __bfloat162float(h3))) << 16);
            *(uint32_t*)(ah + k)     = hiA;
            *(uint32_t*)(ah + k + 2) = hiB;
            *(uint32_t*)(al + k)     = loA;
            *(uint32_t*)(al + k + 2) = loB;
        }
    }
    __syncthreads();

    const int mrow0 = wid * 16;            // warp's 16 rows

    // ldmatrix per-lane address offsets (bytes)
    const int sel   = lid >> 3;            // matrix index 0..3
    const int rowIn = lid & 7;
    // A x4: (r0-7,kLo),(r8-15,kLo),(r0-7,kHi),(r8-15,kHi)
    const uint32_t aoff =
        (uint32_t)(((mrow0 + rowIn + (sel & 1) * 8) * BSTRIDE + (sel >> 1) * 8) * 2);
    // B x4 at n-base j2*16: (nEven,kLo),(nEven,kHi),(nOdd,kLo),(nOdd,kHi)
    const uint32_t boff =
        (uint32_t)((((sel >> 1) * 8 + rowIn) * BSTRIDE + (sel & 1) * 8) * 2);

    const uint32_t aHi = smem_u32(sAh) + aoff;
    const uint32_t aLo = smem_u32(sAl) + aoff;
    const uint32_t bHi = smem_u32(sBh) + boff;
    const uint32_t bLo = smem_u32(sBl) + boff;

    float acc[16][4];
#pragma unroll
    for (int t = 0; t < 16; ++t)
#pragma unroll
        for (int q = 0; q < 4; ++q) acc[t][q] = 0.f;

#pragma unroll
    for (int ks = 0; ks < 8; ++ks) {
        const uint32_t kb = ks * 32;       // 16 k-elems * 2B
        uint32_t ah[4], al[4];
        ldm_x4(ah, aHi + kb);
        ldm_x4(al, aLo + kb);
#pragma unroll
        for (int j2 = 0; j2 < 8; ++j2) {
            const uint32_t nb = j2 * (16 * BSTRIDE * 2);
            uint32_t qh[4], ql[4];
            ldm_x4(qh, bHi + nb + kb);
            ldm_x4(ql, bLo + nb + kb);
            uint32_t be[2] = {qh[0], qh[1]};
            uint32_t bo[2] = {qh[2], qh[3]};
            uint32_t le[2] = {ql[0], ql[1]};
            uint32_t lo2[2] = {ql[2], ql[3]};
            mma_bf16(acc[2 * j2],     ah, be);
            mma_bf16(acc[2 * j2],     ah, le);
            mma_bf16(acc[2 * j2],     al, be);
            mma_bf16(acc[2 * j2 + 1], ah, bo);
            mma_bf16(acc[2 * j2 + 1], ah, lo2);
            mma_bf16(acc[2 * j2 + 1], al, bo);
        }
    }

    // --- Epilogue: scale by dinv, convert fp16, store ---
    const int r1 = row0 + mrow0 + (lid >> 2);
    const int r2 = r1 + 8;
    const int cbase = 2 * (lid & 3);
    const float dv1 = (r1 < n) ? d_dinv[r1] : 0.f;
    const float dv2 = (r2 < n) ? d_dinv[r2] : 0.f;
#pragma unroll
    for (int t = 0; t < 16; ++t) {
        int c = t * 8 + cbase;
        if (r1 < n)
            *(__half2*)(gout + (size_t)r1 * FD + c) =
                __floats2half2_rn(acc[t][0] * dv1, acc[t][1] * dv1);
        if (r2 < n)
            *(__half2*)(gout + (size_t)r2 * FD + c) =
                __floats2half2_rn(acc[t][2] * dv2, acc[t][3] * dv2);
    }
}

// ---------------------------------------------------------------------------
// CSR build: chunked exclusive scan of in-degrees.
__global__ void __launch_bounds__(SCAN_T)
scan_partial(int n) {
    __shared__ int ssum[SCAN_T];
    const int tid  = threadIdx.x;
    const int base = blockIdx.x * SCAN_C + tid * 4;

    int v[4];
#pragma unroll
    for (int i = 0; i < 4; ++i)
        v[i] = (base + i < n) ? d_degi[base + i] : 0;
    int tsum = v[0] + v[1] + v[2] + v[3];
    ssum[tid] = tsum;
    __syncthreads();
    for (int off = 1; off < SCAN_T; off <<= 1) {
        int t = (tid >= off) ? ssum[tid - off] : 0;
        __syncthreads();
        ssum[tid] += t;
        __syncthreads();
    }
    int texcl = ssum[tid] - tsum;
    if (tid == SCAN_T - 1) d_blocksums[blockIdx.x] = ssum[tid];

    int run = texcl;
#pragma unroll
    for (int i = 0; i < 4; ++i) {
        if (base + i < n) d_off[base + i] = run;
        run += v[i];
    }
}

__global__ void scan_blocksums(int nblk) {
    int tid = threadIdx.x;
    int v = (tid < nblk) ? d_blocksums[tid] : 0;
    int orig = v;
#pragma unroll
    for (int o = 1; o < 32; o <<= 1) {
        int t = __shfl_up_sync(0xFFFFFFFFu, v, o);
        if (tid >= o) v += t;
    }
    if (tid < nblk) d_blocksums[tid] = v - orig;
}

__global__ void scan_add(int n, int E) {
    int i = blockIdx.x * blockDim.x + threadIdx.x;
    if (i < n) {
        int v = d_off[i] + d_blocksums[i / SCAN_C];
        d_off[i] = v;
        d_cursor[i] = v;
    }
    if (i == 0) d_off[n] = E;
}

__global__ void scatter_csr(const void* __restrict__ ei, int E) {
    int i = blockIdx.x * blockDim.x + threadIdx.x;
    if (i >= E) return;
    int si = edge_at(ei, i);
    int di = edge_at(ei, (size_t)E + i);
    int pos = atomicAdd(&d_cursor[di], 1);
    d_csr[pos] = si;
}

// ---------------------------------------------------------------------------
// Fused aggregate + epilogue: one warp per dst node, fp16 gather, fp32 out.
//   out[d] = dinv[d] * (Σ_{s∈CSR(d)} g[s] + g[d]) + bias   [+relu]
__global__ void __launch_bounds__(256)
aggregate_csr(const __half* __restrict__ g, const float* __restrict__ bias,
              float* __restrict__ out, int n, int do_relu) {
    const int w = blockIdx.x * 8 + (threadIdx.x >> 5);
    if (w >= n) return;
    const int lane = threadIdx.x & 31;

    // lane covers cols [lane*4, lane*4+4) = 8 bytes fp16
    const uint2* gw = (const uint2*)g + lane;   // row stride: 32 uint2

    float acc0, acc1, acc2, acc3;
    {
        uint2 raw = __ldg(gw + (size_t)w * 32);  // self-loop term
        float2 f0 = __half22float2(*(__half2*)&raw.x);
        float2 f1 = __half22float2(*(__half2*)&raw.y);
        acc0 = f0.x; acc1 = f0.y; acc2 = f1.x; acc3 = f1.y;
    }

    int e = d_off[w];
    const int eend = d_off[w + 1];
    for (; e + 4 <= eend; e += 4) {
        int s0 = __ldg(&d_csr[e]);
        int s1 = __ldg(&d_csr[e + 1]);
        int s2 = __ldg(&d_csr[e + 2]);
        int s3 = __ldg(&d_csr[e + 3]);
        uint2 ra = __ldg(gw + (size_t)s0 * 32);
        uint2 rb = __ldg(gw + (size_t)s1 * 32);
        uint2 rc = __ldg(gw + (size_t)s2 * 32);
        uint2 rd = __ldg(gw + (size_t)s3 * 32);
        float2 a0 = __half22float2(*(__half2*)&ra.x), a1 = __half22float2(*(__half2*)&ra.y);
        float2 b0 = __half22float2(*(__half2*)&rb.x), b1 = __half22float2(*(__half2*)&rb.y);
        float2 c0 = __half22float2(*(__half2*)&rc.x), c1 = __half22float2(*(__half2*)&rc.y);
        float2 d0 = __half22float2(*(__half2*)&rd.x), d1 = __half22float2(*(__half2*)&rd.y);
        acc0 += (a0.x + b0.x) + (c0.x + d0.x);
        acc1 += (a0.y + b0.y) + (c0.y + d0.y);
        acc2 += (a1.x + b1.x) + (c1.x + d1.x);
        acc3 += (a1.y + b1.y) + (c1.y + d1.y);
    }
    for (; e < eend; ++e) {
        int s0 = __ldg(&d_csr[e]);
        uint2 ra = __ldg(gw + (size_t)s0 * 32);
        float2 a0 = __half22float2(*(__half2*)&ra.x), a1 = __half22float2(*(__half2*)&ra.y);
        acc0 += a0.x; acc1 += a0.y; acc2 += a1.x; acc3 += a1.y;
    }

    const float dv = d_dinv[w];
    float4 bs = __ldg((const float4*)bias + lane);
    float4 r;
    r.x = dv * acc0 + bs.x;
    r.y = dv * acc1 + bs.y;
    r.z = dv * acc2 + bs.z;
    r.w = dv * acc3 + bs.w;
    if (do_relu) {
        r.x = fmaxf(r.x, 0.f); r.y = fmaxf(r.y, 0.f);
        r.z = fmaxf(r.z, 0.f); r.w = fmaxf(r.w, 0.f);
    }
    ((float4*)(out + (size_t)w * FD))[lane] = r;
}

// ---------------------------------------------------------------------------
extern "C" void kernel_launch(void* const* d_in, const int* in_sizes, int n_in,
                              void* d_out, int out_size) {
    const float* x  = (const float*)d_in[0];
    const void*  ei = d_in[1];
    const float* W1 = (const float*)d_in[2];
    const float* b1 = (const float*)d_in[3];
    const float* W2 = (const float*)d_in[4];
    const float* b2 = (const float*)d_in[5];
    float* out = (float*)d_out;

    int n = in_sizes[0] / FD;
    if (n > NMAX) n = NMAX;
    int E = in_sizes[1] / 2;
    if (E > EMAX) E = EMAX;

    float *bufA, *bufB;
    cudaGetSymbolAddress((void**)&bufA, d_bufA);
    cudaGetSymbolAddress((void**)&bufB, d_bufB);
    __half* gbuf = (__half*)bufA;

    cudaFuncSetAttribute(gemm_tc,
                         cudaFuncAttributeMaxDynamicSharedMemorySize, GEMM_SMEM);

    const int nblk_scan = (n + SCAN_C - 1) / SCAN_C;
    const int gemm_grid = (n + 63) / 64;

    // 1-3: degree + dinv + W1 split
    zero_deg_detect<<<(n + 255) / 256, 256>>>(ei, W1, n);
    deg_count<<<(E + 255) / 256, 256>>>(ei, E);
    finish_dinv<<<(n + 255) / 256, 256>>>(n);

    // 4 (ncu capture slot): layer-1 HMMA GEMM -> g1 (fp16)
    gemm_tc<<<gemm_grid, 128, GEMM_SMEM>>>(x, gbuf, n);

    // 5: split W2 into the W image buffers (gemm1 done with them)
    w_split<<<64, 256>>>(W2);

    // CSR build
    scan_partial<<<nblk_scan, SCAN_T>>>(n);
    scan_blocksums<<<1, 32>>>(nblk_scan);
    scan_add<<<(n + 255) / 256, 256>>>(n, E);
    scatter_csr<<<(E + 255) / 256, 256>>>(ei, E);

    // layer 1 aggregate (+relu): g1 fp16 -> h fp32
    aggregate_csr<<<(n + 7) / 8, 256>>>(gbuf, b1, bufB, n, 1);

    // layer 2: h -> g2 (fp16) -> out fp32
    gemm_tc<<<gemm_grid, 128, GEMM_SMEM>>>(bufB, gbuf, n);
    aggregate_csr<<<(n + 7) / 8, 256>>>(gbuf, b2, out, n, 0);
}

// round 8
// speedup vs baseline: 10.6826x; 1.0240x over previous
#include <cuda_runtime.h>
#include <cuda_bf16.h>
#include <cuda_fp16.h>
#include <cstdint>

// GNN_9869834846215: two-layer cached GCN.
//   g = dinv ⊙ (h W)  -- persistent double-buffered HMMA bf16x2-split GEMM
//   out[d] = dinv[d]*(Σ_{s∈N(d)} g[s] + g[d]) + b  -- CSR warp-per-node gather

#define NMAX 100000
#define EMAX 1700000
#define FD 128
#define SCAN_T 1024
#define SCAN_C 4096
#define NSM 148

#define BSTRIDE 136                       // bf16 row stride (272B): ldmatrix conflict-free
#define T_SH (128 * BSTRIDE * 2)          // 34816 B per 128-row bf16 tile
#define GEMM_SMEM (6 * T_SH)              // Bh,Bl + 2x(Ah,Al) = 208896 B

// Scratch (__device__ globals per allocation-free rule)
__device__ float d_dinv[NMAX];
__device__ float d_bufA[(size_t)NMAX * FD];   // g (fp16, viewed as half*)
__device__ float d_bufB[(size_t)NMAX * FD];   // h (fp32)
__device__ int   d_degi[NMAX];
__device__ int   d_off[NMAX + 1];
__device__ int   d_cursor[NMAX];
__device__ int   d_csr[EMAX];
__device__ int   d_blocksums[32];
__device__ int   d_is64;
// W^T split into bf16 hi/lo, layout [n][k] with row stride BSTRIDE
__device__ __align__(16) unsigned short d_Whi[128 * BSTRIDE];
__device__ __align__(16) unsigned short d_Wlo[128 * BSTRIDE];

// ---------------------------------------------------------------------------
__device__ __forceinline__ uint32_t smem_u32(const void* p) {
    uint32_t a;
    asm("{ .reg .u64 t; cvta.to.shared.u64 t, %1; cvt.u32.u64 %0, t; }"
        : "=r"(a) : "l"(p));
    return a;
}

__device__ __forceinline__ void ldm_x4(uint32_t* r, uint32_t addr) {
    asm volatile("ldmatrix.sync.aligned.m8n8.x4.shared.b16 {%0,%1,%2,%3}, [%4];"
                 : "=r"(r[0]), "=r"(r[1]), "=r"(r[2]), "=r"(r[3]) : "r"(addr));
}

__device__ __forceinline__ void mma_bf16(float* c, const uint32_t* a,
                                         const uint32_t* b) {
    asm volatile(
        "mma.sync.aligned.m16n8k16.row.col.f32.bf16.bf16.f32 "
        "{%0,%1,%2,%3}, {%4,%5,%6,%7}, {%8,%9}, {%0,%1,%2,%3};"
        : "+f"(c[0]), "+f"(c[1]), "+f"(c[2]), "+f"(c[3])
        : "r"(a[0]), "r"(a[1]), "r"(a[2]), "r"(a[3]), "r"(b[0]), "r"(b[1]));
}

__device__ __forceinline__ unsigned short bfbits(__nv_bfloat16 h) {
    return __bfloat16_as_ushort(h);
}

// ---------------------------------------------------------------------------
// Split one W element into the hi/lo B images. B[n][k] = W[k][n].
__device__ __forceinline__ void w_split_elem(const float* W, int idx) {
    int nn = idx & 127, kk = idx >> 7;
    float v = W[kk * FD + nn];
    __nv_bfloat16 hi = __float2bfloat16_rn(v);
    __nv_bfloat16 lo = __float2bfloat16_rn(v - __bfloat162float(hi));
    d_Whi[nn * BSTRIDE + kk] = bfbits(hi);
    d_Wlo[nn * BSTRIDE + kk] = bfbits(lo);
}

__global__ void w_split(const float* __restrict__ W) {
    int idx = blockIdx.x * 256 + threadIdx.x;
    if (idx < 16384) w_split_elem(W, idx);
}

// zero deg counters + edge dtype detect + W1 split
__global__ void zero_deg_detect(const void* __restrict__ ei,
                                const float* __restrict__ W1, int n) {
    int i = blockIdx.x * blockDim.x + threadIdx.x;
    if (i < n) d_degi[i] = 0;
    if (i < 16384) w_split_elem(W1, i);
    if (i == 0) {
        const int2* p = (const int2*)ei;
        int is64 = 1;
        for (int j = 0; j < 64; ++j)
            if (p[j].y != 0) { is64 = 0; break; }
        d_is64 = is64;
    }
}

__device__ __forceinline__ int edge_at(const void* ei, size_t idx) {
    return d_is64 ? (int)((const long long*)ei)[idx] : ((const int*)ei)[idx];
}

__global__ void deg_count(const void* __restrict__ ei, int E) {
    int i = blockIdx.x * blockDim.x + threadIdx.x;
    if (i >= E) return;
    atomicAdd(&d_degi[edge_at(ei, (size_t)E + i)], 1);
}

__global__ void finish_dinv(int n) {
    int i = blockIdx.x * blockDim.x + threadIdx.x;
    if (i < n) d_dinv[i] = rsqrtf((float)d_degi[i] + 1.0f);
}

// ---------------------------------------------------------------------------
// Persistent HMMA GEMM: gout[row] = fp16( dinv[row] * (in[row] @ W) ).
// One block/SM; B staged once; A tiles double-buffered with register prefetch.
__global__ void __launch_bounds__(256)
gemm_tc(const float* __restrict__ in, __half* __restrict__ gout,
        int n, int ntiles) {
    extern __shared__ char dsm[];
    char* sBh = dsm;
    char* sBl = dsm + T_SH;
    char* sAh[2] = {dsm + 2 * T_SH, dsm + 4 * T_SH};
    char* sAl[2] = {dsm + 3 * T_SH, dsm + 5 * T_SH};

    const int tid = threadIdx.x;
    const int wid = tid >> 5;
    const int lid = tid & 31;
    const int r  = tid >> 1;          // A row handled by this thread
    const int h  = tid & 1;           // which 64-col half

    // --- Stage B once: linear copy of pre-split global images ---
    {
        const float4* wh = (const float4*)d_Whi;
        const float4* wl = (const float4*)d_Wlo;
        float4* bh = (float4*)sBh;
        float4* bl = (float4*)sBl;
        for (int i = tid; i < T_SH / 16; i += 256) { bh[i] = wh[i]; bl[i] = wl[i]; }
    }

    // --- Warp tiling constants (R6-validated mapping) ---
    const int mrow0 = (wid >> 2) * 64;     // 0 or 64
    const int ncol0 = (wid & 3) * 32;      // 0,32,64,96
    const int sel   = lid >> 3;
    const int rowIn = lid & 7;
    const uint32_t aoff =
        (uint32_t)(((mrow0 + rowIn + (sel & 1) * 8) * BSTRIDE + (sel >> 1) * 8) * 2);
    const uint32_t boff =
        (uint32_t)(((ncol0 + (sel >> 1) * 8 + rowIn) * BSTRIDE + (sel & 1) * 8) * 2);
    const uint32_t bHi = smem_u32(sBh) + boff;
    const uint32_t bLo = smem_u32(sBl) + boff;
    const uint32_t aHiB[2] = {smem_u32(sAh[0]) + aoff, smem_u32(sAh[1]) + aoff};
    const uint32_t aLoB[2] = {smem_u32(sAl[0]) + aoff, smem_u32(sAl[1]) + aoff};

    float4 pf[16];

    // --- Prologue: prefetch + convert first tile into buf 0 ---
    int t = blockIdx.x;
    if (t < ntiles) {
        int gr = t * 128 + r;
        if (gr >= n) gr = n - 1;
        const float4* src = (const float4*)(in + (size_t)gr * FD) + h * 16;
#pragma unroll
        for (int i = 0; i < 16; ++i) pf[i] = __ldg(src + i);
        unsigned short* ah = (unsigned short*)sAh[0] + r * BSTRIDE + h * 64;
        unsigned short* al = (unsigned short*)sAl[0] + r * BSTRIDE + h * 64;
#pragma unroll
        for (int i = 0; i < 16; ++i) {
            float4 v = pf[i];
            __nv_bfloat16 h0 = __float2bfloat16_rn(v.x);
            __nv_bfloat16 h1 = __float2bfloat16_rn(v.y);
            __nv_bfloat16 h2 = __float2bfloat16_rn(v.z);
            __nv_bfloat16 h3 = __float2bfloat16_rn(v.w);
            *(uint32_t*)(ah + i * 4)     = (uint32_t)bfbits(h0) | ((uint32_t)bfbits(h1) << 16);
            *(uint32_t*)(ah + i * 4 + 2) = (uint32_t)bfbits(h2) | ((uint32_t)bfbits(h3) << 16);
            *(uint32_t*)(al + i * 4) =
                (uint32_t)bfbits(__float2bfloat16_rn(v.x - __bfloat162float(h0))) |
                ((uint32_t)bfbits(__float2bfloat16_rn(v.y - __bfloat162float(h1))) << 16);
            *(uint32_t*)(al + i * 4 + 2) =
                (uint32_t)bfbits(__float2bfloat16_rn(v.z - __bfloat162float(h2))) |
                ((uint32_t)bfbits(__float2bfloat16_rn(v.w - __bfloat162float(h3))) << 16);
        }
    }
    __syncthreads();

    int cur = 0;
    while (t < ntiles) {
        const int tn = t + gridDim.x;

        // Prefetch next tile into registers (latency hidden by MMA phase)
        if (tn < ntiles) {
            int gr = tn * 128 + r;
            if (gr >= n) gr = n - 1;
            const float4* src = (const float4*)(in + (size_t)gr * FD) + h * 16;
#pragma unroll
            for (int i = 0; i < 16; ++i) pf[i] = __ldg(src + i);
        }

        // --- MMA phase on buf[cur] ---
        const uint32_t aHi = aHiB[cur];
        const uint32_t aLo = aLoB[cur];
        float acc[4][4][4];
#pragma unroll
        for (int i = 0; i < 4; ++i)
#pragma unroll
            for (int j = 0; j < 4; ++j)
#pragma unroll
                for (int q = 0; q < 4; ++q) acc[i][j][q] = 0.f;

#pragma unroll
        for (int ks = 0; ks < 8; ++ks) {
            const uint32_t kb = ks * 32;
            uint32_t ah[4][4], al[4][4], bh2[4][2], bl2[4][2];
#pragma unroll
            for (int i = 0; i < 4; ++i) {
                ldm_x4(ah[i], aHi + i * (16 * BSTRIDE * 2) + kb);
                ldm_x4(al[i], aLo + i * (16 * BSTRIDE * 2) + kb);
            }
#pragma unroll
            for (int j2 = 0; j2 < 2; ++j2) {
                uint32_t q[4];
                ldm_x4(q, bHi + j2 * (16 * BSTRIDE * 2) + kb);
                bh2[2 * j2][0] = q[0]; bh2[2 * j2][1] = q[1];
                bh2[2 * j2 + 1][0] = q[2]; bh2[2 * j2 + 1][1] = q[3];
                ldm_x4(q, bLo + j2 * (16 * BSTRIDE * 2) + kb);
                bl2[2 * j2][0] = q[0]; bl2[2 * j2][1] = q[1];
                bl2[2 * j2 + 1][0] = q[2]; bl2[2 * j2 + 1][1] = q[3];
            }
#pragma unroll
            for (int i = 0; i < 4; ++i)
#pragma unroll
                for (int j = 0; j < 4; ++j) {
                    mma_bf16(acc[i][j], ah[i], bh2[j]);
                    mma_bf16(acc[i][j], ah[i], bl2[j]);
                    mma_bf16(acc[i][j], al[i], bh2[j]);
                }
        }

        // --- Epilogue: scale by dinv, convert fp16, store ---
        {
            const int row0 = t * 128;
            const int rb = row0 + mrow0 + (lid >> 2);
            const int cbase = ncol0 + 2 * (lid & 3);
#pragma unroll
            for (int i = 0; i < 4; ++i) {
                int r1 = rb + 16 * i;
                int r2 = r1 + 8;
                float dv1 = (r1 < n) ? d_dinv[r1] : 0.f;
                float dv2 = (r2 < n) ? d_dinv[r2] : 0.f;
#pragma unroll
                for (int j = 0; j < 4; ++j) {
                    int c = cbase + 8 * j;
                    if (r1 < n)
                        *(__half2*)(gout + (size_t)r1 * FD + c) =
                            __floats2half2_rn(acc[i][j][0] * dv1, acc[i][j][1] * dv1);
                    if (r2 < n)
                        *(__half2*)(gout + (size_t)r2 * FD + c) =
                            __floats2half2_rn(acc[i][j][2] * dv2, acc[i][j][3] * dv2);
                }
            }
        }

        // --- Convert prefetched regs into buf[cur^1] ---
        if (tn < ntiles) {
            unsigned short* ah = (unsigned short*)sAh[cur ^ 1] + r * BSTRIDE + h * 64;
            unsigned short* al = (unsigned short*)sAl[cur ^ 1] + r * BSTRIDE + h * 64;
#pragma unroll
            for (int i = 0; i < 16; ++i) {
                float4 v = pf[i];
                __nv_bfloat16 h0 = __float2bfloat16_rn(v.x);
                __nv_bfloat16 h1 = __float2bfloat16_rn(v.y);
                __nv_bfloat16 h2 = __float2bfloat16_rn(v.z);
                __nv_bfloat16 h3 = __float2bfloat16_rn(v.w);
                *(uint32_t*)(ah + i * 4)     = (uint32_t)bfbits(h0) | ((uint32_t)bfbits(h1) << 16);
                *(uint32_t*)(ah + i * 4 + 2) = (uint32_t)bfbits(h2) | ((uint32_t)bfbits(h3) << 16);
                *(uint32_t*)(al + i * 4) =
                    (uint32_t)bfbits(__float2bfloat16_rn(v.x - __bfloat162float(h0))) |
                    ((uint32_t)bfbits(__float2bfloat16_rn(v.y - __bfloat162float(h1))) << 16);
                *(uint32_t*)(al + i * 4 + 2) =
                    (uint32_t)bfbits(__float2bfloat16_rn(v.z - __bfloat162float(h2))) |
                    ((uint32_t)bfbits(__float2bfloat16_rn(v.w - __bfloat162float(h3))) << 16);
            }
        }
        __syncthreads();
        cur ^= 1;
        t = tn;
    }
}

// ---------------------------------------------------------------------------
// CSR build: chunked exclusive scan of in-degrees.
__global__ void __launch_bounds__(SCAN_T)
scan_partial(int n) {
    __shared__ int ssum[SCAN_T];
    const int tid  = threadIdx.x;
    const int base = blockIdx.x * SCAN_C + tid * 4;

    int v[4];
#pragma unroll
    for (int i = 0; i < 4; ++i)
        v[i] = (base + i < n) ? d_degi[base + i] : 0;
    int tsum = v[0] + v[1] + v[2] + v[3];
    ssum[tid] = tsum;
    __syncthreads();
    for (int off = 1; off < SCAN_T; off <<= 1) {
        int t = (tid >= off) ? ssum[tid - off] : 0;
        __syncthreads();
        ssum[tid] += t;
        __syncthreads();
    }
    int texcl = ssum[tid] - tsum;
    if (tid == SCAN_T - 1) d_blocksums[blockIdx.x] = ssum[tid];

    int run = texcl;
#pragma unroll
    for (int i = 0; i < 4; ++i) {
        if (base + i < n) d_off[base + i] = run;
        run += v[i];
    }
}

__global__ void scan_blocksums(int nblk) {
    int tid = threadIdx.x;
    int v = (tid < nblk) ? d_blocksums[tid] : 0;
    int orig = v;
#pragma unroll
    for (int o = 1; o < 32; o <<= 1) {
        int t = __shfl_up_sync(0xFFFFFFFFu, v, o);
        if (tid >= o) v += t;
    }
    if (tid < nblk) d_blocksums[tid] = v - orig;
}

__global__ void scan_add(int n, int E) {
    int i = blockIdx.x * blockDim.x + threadIdx.x;
    if (i < n) {
        int v = d_off[i] + d_blocksums[i / SCAN_C];
        d_off[i] = v;
        d_cursor[i] = v;
    }
    if (i == 0) d_off[n] = E;
}

__global__ void scatter_csr(const void* __restrict__ ei, int E) {
    int i = blockIdx.x * blockDim.x + threadIdx.x;
    if (i >= E) return;
    int si = edge_at(ei, i);
    int di = edge_at(ei, (size_t)E + i);
    int pos = atomicAdd(&d_cursor[di], 1);
    d_csr[pos] = si;
}

// ---------------------------------------------------------------------------
// Fused aggregate + epilogue: one warp per dst node, fp16 gather, fp32 out.
__global__ void __launch_bounds__(256)
aggregate_csr(const __half* __restrict__ g, const float* __restrict__ bias,
              float* __restrict__ out, int n, int do_relu) {
    const int w = blockIdx.x * 8 + (threadIdx.x >> 5);
    if (w >= n) return;
    const int lane = threadIdx.x & 31;

    const uint2* gw = (const uint2*)g + lane;   // row stride: 32 uint2

    float acc0, acc1, acc2, acc3;
    {
        uint2 raw = __ldg(gw + (size_t)w * 32);  // self-loop term
        float2 f0 = __half22float2(*(__half2*)&raw.x);
        float2 f1 = __half22float2(*(__half2*)&raw.y);
        acc0 = f0.x; acc1 = f0.y; acc2 = f1.x; acc3 = f1.y;
    }

    int e = d_off[w];
    const int eend = d_off[w + 1];
    for (; e + 4 <= eend; e += 4) {
        int s0 = __ldg(&d_csr[e]);
        int s1 = __ldg(&d_csr[e + 1]);
        int s2 = __ldg(&d_csr[e + 2]);
        int s3 = __ldg(&d_csr[e + 3]);
        uint2 ra = __ldg(gw + (size_t)s0 * 32);
        uint2 rb = __ldg(gw + (size_t)s1 * 32);
        uint2 rc = __ldg(gw + (size_t)s2 * 32);
        uint2 rd = __ldg(gw + (size_t)s3 * 32);
        float2 a0 = __half22float2(*(__half2*)&ra.x), a1 = __half22float2(*(__half2*)&ra.y);
        float2 b0 = __half22float2(*(__half2*)&rb.x), b1 = __half22float2(*(__half2*)&rb.y);
        float2 c0 = __half22float2(*(__half2*)&rc.x), c1 = __half22float2(*(__half2*)&rc.y);
        float2 d0 = __half22float2(*(__half2*)&rd.x), d1 = __half22float2(*(__half2*)&rd.y);
        acc0 += (a0.x + b0.x) + (c0.x + d0.x);
        acc1 += (a0.y + b0.y) + (c0.y + d0.y);
        acc2 += (a1.x + b1.x) + (c1.x + d1.x);
        acc3 += (a1.y + b1.y) + (c1.y + d1.y);
    }
    for (; e < eend; ++e) {
        int s0 = __ldg(&d_csr[e]);
        uint2 ra = __ldg(gw + (size_t)s0 * 32);
        float2 a0 = __half22float2(*(__half2*)&ra.x), a1 = __half22float2(*(__half2*)&ra.y);
        acc0 += a0.x; acc1 += a0.y; acc2 += a1.x; acc3 += a1.y;
    }

    const float dv = d_dinv[w];
    float4 bs = __ldg((const float4*)bias + lane);
    float4 r;
    r.x = dv * acc0 + bs.x;
    r.y = dv * acc1 + bs.y;
    r.z = dv * acc2 + bs.z;
    r.w = dv * acc3 + bs.w;
    if (do_relu) {
        r.x = fmaxf(r.x, 0.f); r.y = fmaxf(r.y, 0.f);
        r.z = fmaxf(r.z, 0.f); r.w = fmaxf(r.w, 0.f);
    }
    ((float4*)(out + (size_t)w * FD))[lane] = r;
}

// ---------------------------------------------------------------------------
extern "C" void kernel_launch(void* const* d_in, const int* in_sizes, int n_in,
                              void* d_out, int out_size) {
    const float* x  = (const float*)d_in[0];
    const void*  ei = d_in[1];
    const float* W1 = (const float*)d_in[2];
    const float* b1 = (const float*)d_in[3];
    const float* W2 = (const float*)d_in[4];
    const float* b2 = (const float*)d_in[5];
    float* out = (float*)d_out;

    int n = in_sizes[0] / FD;
    if (n > NMAX) n = NMAX;
    int E = in_sizes[1] / 2;
    if (E > EMAX) E = EMAX;

    float *bufA, *bufB;
    cudaGetSymbolAddress((void**)&bufA, d_bufA);
    cudaGetSymbolAddress((void**)&bufB, d_bufB);
    __half* gbuf = (__half*)bufA;

    cudaFuncSetAttribute(gemm_tc,
                         cudaFuncAttributeMaxDynamicSharedMemorySize, GEMM_SMEM);

    const int nblk_scan = (n + SCAN_C - 1) / SCAN_C;
    const int ntiles = (n + 127) / 128;
    const int ggrid = (ntiles < NSM) ? ntiles : NSM;

    // 1-3: degree + dinv + W1 split
    zero_deg_detect<<<(n + 255) / 256, 256>>>(ei, W1, n);
    deg_count<<<(E + 255) / 256, 256>>>(ei, E);
    finish_dinv<<<(n + 255) / 256, 256>>>(n);

    // 4 (ncu capture slot): layer-1 persistent HMMA GEMM -> g1 (fp16)
    gemm_tc<<<ggrid, 256, GEMM_SMEM>>>(x, gbuf, n, ntiles);

    // 5: split W2 into the W image buffers (gemm1 done with them)
    w_split<<<64, 256>>>(W2);

    // CSR build
    scan_partial<<<nblk_scan, SCAN_T>>>(n);
    scan_blocksums<<<1, 32>>>(nblk_scan);
    scan_add<<<(n + 255) / 256, 256>>>(n, E);
    scatter_csr<<<(E + 255) / 256, 256>>>(ei, E);

    // layer 1 aggregate (+relu): g1 fp16 -> h fp32
    aggregate_csr<<<(n + 7) / 8, 256>>>(gbuf, b1, bufB, n, 1);

    // layer 2: h -> g2 (fp16) -> out fp32
    gemm_tc<<<ggrid, 256, GEMM_SMEM>>>(bufB, gbuf, n, ntiles);
    aggregate_csr<<<(n + 7) / 8, 256>>>(gbuf, b2, out, n, 0);
}

// round 9
// speedup vs baseline: 12.0135x; 1.1246x over previous
#include <cuda_runtime.h>
#include <cuda_bf16.h>
#include <cuda_fp16.h>
#include <cstdint>

// GNN_9869834846215: two-layer cached GCN.
//   g = dinv ⊙ (h W)  -- persistent HMMA bf16x2-split GEMM, 2 blocks/SM
//   out[d] = dinv[d]*(Σ_{s∈N(d)} g[s] + g[d]) + b  -- CSR warp-per-node gather

#define NMAX 100000
#define EMAX 1700000
#define FD 128
#define SCAN_T 1024
#define SCAN_C 4096
#define NSM 148

#define BSTRIDE 136                       // bf16 row stride (272B): ldmatrix conflict-free
#define T_SH (128 * BSTRIDE * 2)          // 34816 B (128-row bf16 tile: B images)
#define A_SH (64 * BSTRIDE * 2)           // 17408 B (64-row bf16 tile: A images)
#define GEMM_SMEM (2 * T_SH + 2 * A_SH)   // 104448 B -> 2 blocks/SM (208.9KB/SM)

// Scratch (__device__ globals per allocation-free rule)
__device__ float d_dinv[NMAX];
__device__ float d_bufA[(size_t)NMAX * FD];   // g (fp16, viewed as half*)
__device__ float d_bufB[(size_t)NMAX * FD];   // h (fp32)
__device__ int   d_degi[NMAX];
__device__ int   d_off[NMAX + 1];
__device__ int   d_cursor[NMAX];
__device__ int   d_csr[EMAX];
__device__ int   d_blocksums[32];
__device__ int   d_is64;
// W^T split into bf16 hi/lo, layout [n][k] with row stride BSTRIDE
__device__ __align__(16) unsigned short d_Whi[128 * BSTRIDE];
__device__ __align__(16) unsigned short d_Wlo[128 * BSTRIDE];

// ---------------------------------------------------------------------------
__device__ __forceinline__ uint32_t smem_u32(const void* p) {
    uint32_t a;
    asm("{ .reg .u64 t; cvta.to.shared.u64 t, %1; cvt.u32.u64 %0, t; }"
        : "=r"(a) : "l"(p));
    return a;
}

__device__ __forceinline__ void ldm_x4(uint32_t* r, uint32_t addr) {
    asm volatile("ldmatrix.sync.aligned.m8n8.x4.shared.b16 {%0,%1,%2,%3}, [%4];"
                 : "=r"(r[0]), "=r"(r[1]), "=r"(r[2]), "=r"(r[3]) : "r"(addr));
}

__device__ __forceinline__ void mma_bf16(float* c, const uint32_t* a,
                                         const uint32_t* b) {
    asm volatile(
        "mma.sync.aligned.m16n8k16.row.col.f32.bf16.bf16.f32 "
        "{%0,%1,%2,%3}, {%4,%5,%6,%7}, {%8,%9}, {%0,%1,%2,%3};"
        : "+f"(c[0]), "+f"(c[1]), "+f"(c[2]), "+f"(c[3])
        : "r"(a[0]), "r"(a[1]), "r"(a[2]), "r"(a[3]), "r"(b[0]), "r"(b[1]));
}

__device__ __forceinline__ unsigned short bfbits(__nv_bfloat16 h) {
    return __bfloat16_as_ushort(h);
}

// ---------------------------------------------------------------------------
// Split one W element into the hi/lo B images. B[n][k] = W[k][n].
__device__ __forceinline__ void w_split_elem(const float* W, int idx) {
    int nn = idx & 127, kk = idx >> 7;
    float v = W[kk * FD + nn];
    __nv_bfloat16 hi = __float2bfloat16_rn(v);
    __nv_bfloat16 lo = __float2bfloat16_rn(v - __bfloat162float(hi));
    d_Whi[nn * BSTRIDE + kk] = bfbits(hi);
    d_Wlo[nn * BSTRIDE + kk] = bfbits(lo);
}

__global__ void w_split(const float* __restrict__ W) {
    int idx = blockIdx.x * 256 + threadIdx.x;
    if (idx < 16384) w_split_elem(W, idx);
}

// zero deg counters + edge dtype detect + W1 split
__global__ void zero_deg_detect(const void* __restrict__ ei,
                                const float* __restrict__ W1, int n) {
    int i = blockIdx.x * blockDim.x + threadIdx.x;
    if (i < n) d_degi[i] = 0;
    if (i < 16384) w_split_elem(W1, i);
    if (i == 0) {
        const int2* p = (const int2*)ei;
        int is64 = 1;
        for (int j = 0; j < 64; ++j)
            if (p[j].y != 0) { is64 = 0; break; }
        d_is64 = is64;
    }
}

__device__ __forceinline__ int edge_at(const void* ei, size_t idx) {
    return d_is64 ? (int)((const long long*)ei)[idx] : ((const int*)ei)[idx];
}

__global__ void deg_count(const void* __restrict__ ei, int E) {
    int i = blockIdx.x * blockDim.x + threadIdx.x;
    if (i >= E) return;
    atomicAdd(&d_degi[edge_at(ei, (size_t)E + i)], 1);
}

__global__ void finish_dinv(int n) {
    int i = blockIdx.x * blockDim.x + threadIdx.x;
    if (i < n) d_dinv[i] = rsqrtf((float)d_degi[i] + 1.0f);
}

// ---------------------------------------------------------------------------
// Persistent HMMA GEMM: gout[row] = fp16( dinv[row] * (in[row] @ W) ).
// 64-row tiles, 8 warps (warp tile 32x32), 2 blocks/SM (16 MMA warps/SM).
// B images staged once per block; A staged per tile (simple sync flow).
__global__ void __launch_bounds__(256, 2)
gemm_tc(const float* __restrict__ in, __half* __restrict__ gout,
        int n, int ntiles) {
    extern __shared__ char dsm[];
    char* sBh = dsm;
    char* sBl = dsm + T_SH;
    char* sAh = dsm + 2 * T_SH;
    char* sAl = dsm + 2 * T_SH + A_SH;

    const int tid = threadIdx.x;
    const int wid = tid >> 5;
    const int lid = tid & 31;

    // --- Stage B once: linear copy of pre-split global images ---
    {
        const float4* wh = (const float4*)d_Whi;
        const float4* wl = (const float4*)d_Wlo;
        float4* bh = (float4*)sBh;
        float4* bl = (float4*)sBl;
        for (int i = tid; i < T_SH / 16; i += 256) { bh[i] = wh[i]; bl[i] = wl[i]; }
    }

    // --- Warp tiling: warp tile 32 rows x 32 cols ---
    const int mrow0 = (wid >> 2) * 32;     // 0 or 32
    const int ncol0 = (wid & 3) * 32;      // 0,32,64,96
    const int sel   = lid >> 3;
    const int rowIn = lid & 7;
    const uint32_t aoff =
        (uint32_t)(((mrow0 + rowIn + (sel & 1) * 8) * BSTRIDE + (sel >> 1) * 8) * 2);
    const uint32_t boff =
        (uint32_t)(((ncol0 + (sel >> 1) * 8 + rowIn) * BSTRIDE + (sel & 1) * 8) * 2);
    const uint32_t aHi = smem_u32(sAh) + aoff;
    const uint32_t aLo = smem_u32(sAl) + aoff;
    const uint32_t bHi = smem_u32(sBh) + boff;
    const uint32_t bLo = smem_u32(sBl) + boff;

    // A staging: thread -> (row, col-quarter)
    const int ar = tid >> 2;           // 0..63
    const int ac = tid & 3;            // col quarter (32 cols)

    for (int t = blockIdx.x; t < ntiles; t += gridDim.x) {
        // --- Stage A tile: load fp32, split hi/lo bf16 ---
        {
            int gr = t * 64 + ar;
            if (gr >= n) gr = n - 1;
            const float4* src = (const float4*)(in + (size_t)gr * FD) + ac * 8;
            unsigned short* ah = (unsigned short*)sAh + ar * BSTRIDE + ac * 32;
            unsigned short* al = (unsigned short*)sAl + ar * BSTRIDE + ac * 32;
#pragma unroll
            for (int i = 0; i < 8; ++i) {
                float4 v = __ldg(src + i);
                __nv_bfloat16 h0 = __float2bfloat16_rn(v.x);
                __nv_bfloat16 h1 = __float2bfloat16_rn(v.y);
                __nv_bfloat16 h2 = __float2bfloat16_rn(v.z);
                __nv_bfloat16 h3 = __float2bfloat16_rn(v.w);
                *(uint32_t*)(ah + i * 4)     = (uint32_t)bfbits(h0) | ((uint32_t)bfbits(h1) << 16);
                *(uint32_t*)(ah + i * 4 + 2) = (uint32_t)bfbits(h2) | ((uint32_t)bfbits(h3) << 16);
                *(uint32_t*)(al + i * 4) =
                    (uint32_t)bfbits(__float2bfloat16_rn(v.x - __bfloat162float(h0))) |
                    ((uint32_t)bfbits(__float2bfloat16_rn(v.y - __bfloat162float(h1))) << 16);
                *(uint32_t*)(al + i * 4 + 2) =
                    (uint32_t)bfbits(__float2bfloat16_rn(v.z - __bfloat162float(h2))) |
                    ((uint32_t)bfbits(__float2bfloat16_rn(v.w - __bfloat162float(h3))) << 16);
            }
        }
        __syncthreads();

        // --- MMA phase ---
        float acc[2][4][4];
#pragma unroll
        for (int i = 0; i < 2; ++i)
#pragma unroll
            for (int j = 0; j < 4; ++j)
#pragma unroll
                for (int q = 0; q < 4; ++q) acc[i][j][q] = 0.f;

#pragma unroll
        for (int ks = 0; ks < 8; ++ks) {
            const uint32_t kb = ks * 32;
            uint32_t ah[2][4], al[2][4], bh2[4][2], bl2[4][2];
#pragma unroll
            for (int i = 0; i < 2; ++i) {
                ldm_x4(ah[i], aHi + i * (16 * BSTRIDE * 2) + kb);
                ldm_x4(al[i], aLo + i * (16 * BSTRIDE * 2) + kb);
            }
#pragma unroll
            for (int j2 = 0; j2 < 2; ++j2) {
                uint32_t q[4];
                ldm_x4(q, bHi + j2 * (16 * BSTRIDE * 2) + kb);
                bh2[2 * j2][0] = q[0]; bh2[2 * j2][1] = q[1];
                bh2[2 * j2 + 1][0] = q[2]; bh2[2 * j2 + 1][1] = q[3];
                ldm_x4(q, bLo + j2 * (16 * BSTRIDE * 2) + kb);
                bl2[2 * j2][0] = q[0]; bl2[2 * j2][1] = q[1];
                bl2[2 * j2 + 1][0] = q[2]; bl2[2 * j2 + 1][1] = q[3];
            }
#pragma unroll
            for (int i = 0; i < 2; ++i)
#pragma unroll
                for (int j = 0; j < 4; ++j) {
                    mma_bf16(acc[i][j], ah[i], bh2[j]);
                    mma_bf16(acc[i][j], ah[i], bl2[j]);
                    mma_bf16(acc[i][j], al[i], bh2[j]);
                }
        }

        // --- Epilogue: scale by dinv, convert fp16, store ---
        {
            const int rb = t * 64 + mrow0 + (lid >> 2);
            const int cbase = ncol0 + 2 * (lid & 3);
#pragma unroll
            for (int i = 0; i < 2; ++i) {
                int r1 = rb + 16 * i;
                int r2 = r1 + 8;
                float dv1 = (r1 < n) ? d_dinv[r1] : 0.f;
                float dv2 = (r2 < n) ? d_dinv[r2] : 0.f;
#pragma unroll
                for (int j = 0; j < 4; ++j) {
                    int c = cbase + 8 * j;
                    if (r1 < n)
                        *(__half2*)(gout + (size_t)r1 * FD + c) =
                            __floats2half2_rn(acc[i][j][0] * dv1, acc[i][j][1] * dv1);
                    if (r2 < n)
                        *(__half2*)(gout + (size_t)r2 * FD + c) =
                            __floats2half2_rn(acc[i][j][2] * dv2, acc[i][j][3] * dv2);
                }
            }
        }
        __syncthreads();
    }
}

// ---------------------------------------------------------------------------
// CSR build: chunked exclusive scan of in-degrees.
__global__ void __launch_bounds__(SCAN_T)
scan_partial(int n) {
    __shared__ int ssum[SCAN_T];
    const int tid  = threadIdx.x;
    const int base = blockIdx.x * SCAN_C + tid * 4;

    int v[4];
#pragma unroll
    for (int i = 0; i < 4; ++i)
        v[i] = (base + i < n) ? d_degi[base + i] : 0;
    int tsum = v[0] + v[1] + v[2] + v[3];
    ssum[tid] = tsum;
    __syncthreads();
    for (int off = 1; off < SCAN_T; off <<= 1) {
        int t = (tid >= off) ? ssum[tid - off] : 0;
        __syncthreads();
        ssum[tid] += t;
        __syncthreads();
    }
    int texcl = ssum[tid] - tsum;
    if (tid == SCAN_T - 1) d_blocksums[blockIdx.x] = ssum[tid];

    int run = texcl;
#pragma unroll
    for (int i = 0; i < 4; ++i) {
        if (base + i < n) d_off[base + i] = run;
        run += v[i];
    }
}

__global__ void scan_blocksums(int nblk) {
    int tid = threadIdx.x;
    int v = (tid < nblk) ? d_blocksums[tid] : 0;
    int orig = v;
#pragma unroll
    for (int o = 1; o < 32; o <<= 1) {
        int t = __shfl_up_sync(0xFFFFFFFFu, v, o);
        if (tid >= o) v += t;
    }
    if (tid < nblk) d_blocksums[tid] = v - orig;
}

__global__ void scan_add(int n, int E) {
    int i = blockIdx.x * blockDim.x + threadIdx.x;
    if (i < n) {
        int v = d_off[i] + d_blocksums[i / SCAN_C];
        d_off[i] = v;
        d_cursor[i] = v;
    }
    if (i == 0) d_off[n] = E;
}

__global__ void scatter_csr(const void* __restrict__ ei, int E) {
    int i = blockIdx.x * blockDim.x + threadIdx.x;
    if (i >= E) return;
    int si = edge_at(ei, i);
    int di = edge_at(ei, (size_t)E + i);
    int pos = atomicAdd(&d_cursor[di], 1);
    d_csr[pos] = si;
}

// ---------------------------------------------------------------------------
// Fused aggregate + epilogue: one warp per dst node, fp16 gather, fp32 out.
__global__ void __launch_bounds__(256)
aggregate_csr(const __half* __restrict__ g, const float* __restrict__ bias,
              float* __restrict__ out, int n, int do_relu) {
    const int w = blockIdx.x * 8 + (threadIdx.x >> 5);
    if (w >= n) return;
    const int lane = threadIdx.x & 31;

    const uint2* gw = (const uint2*)g + lane;   // row stride: 32 uint2

    float acc0, acc1, acc2, acc3;
    {
        uint2 raw = __ldg(gw + (size_t)w * 32);  // self-loop term
        float2 f0 = __half22float2(*(__half2*)&raw.x);
        float2 f1 = __half22float2(*(__half2*)&raw.y);
        acc0 = f0.x; acc1 = f0.y; acc2 = f1.x; acc3 = f1.y;
    }

    int e = d_off[w];
    const int eend = d_off[w + 1];
    for (; e + 4 <= eend; e += 4) {
        int s0 = __ldg(&d_csr[e]);
        int s1 = __ldg(&d_csr[e + 1]);
        int s2 = __ldg(&d_csr[e + 2]);
        int s3 = __ldg(&d_csr[e + 3]);
        uint2 ra = __ldg(gw + (size_t)s0 * 32);
        uint2 rb = __ldg(gw + (size_t)s1 * 32);
        uint2 rc = __ldg(gw + (size_t)s2 * 32);
        uint2 rd = __ldg(gw + (size_t)s3 * 32);
        float2 a0 = __half22float2(*(__half2*)&ra.x), a1 = __half22float2(*(__half2*)&ra.y);
        float2 b0 = __half22float2(*(__half2*)&rb.x), b1 = __half22float2(*(__half2*)&rb.y);
        float2 c0 = __half22float2(*(__half2*)&rc.x), c1 = __half22float2(*(__half2*)&rc.y);
        float2 d0 = __half22float2(*(__half2*)&rd.x), d1 = __half22float2(*(__half2*)&rd.y);
        acc0 += (a0.x + b0.x) + (c0.x + d0.x);
        acc1 += (a0.y + b0.y) + (c0.y + d0.y);
        acc2 += (a1.x + b1.x) + (c1.x + d1.x);
        acc3 += (a1.y + b1.y) + (c1.y + d1.y);
    }
    for (; e < eend; ++e) {
        int s0 = __ldg(&d_csr[e]);
        uint2 ra = __ldg(gw + (size_t)s0 * 32);
        float2 a0 = __half22float2(*(__half2*)&ra.x), a1 = __half22float2(*(__half2*)&ra.y);
        acc0 += a0.x; acc1 += a0.y; acc2 += a1.x; acc3 += a1.y;
    }

    const float dv = d_dinv[w];
    float4 bs = __ldg((const float4*)bias + lane);
    float4 r;
    r.x = dv * acc0 + bs.x;
    r.y = dv * acc1 + bs.y;
    r.z = dv * acc2 + bs.z;
    r.w = dv * acc3 + bs.w;
    if (do_relu) {
        r.x = fmaxf(r.x, 0.f); r.y = fmaxf(r.y, 0.f);
        r.z = fmaxf(r.z, 0.f); r.w = fmaxf(r.w, 0.f);
    }
    ((float4*)(out + (size_t)w * FD))[lane] = r;
}

// ---------------------------------------------------------------------------
extern "C" void kernel_launch(void* const* d_in, const int* in_sizes, int n_in,
                              void* d_out, int out_size) {
    const float* x  = (const float*)d_in[0];
    const void*  ei = d_in[1];
    const float* W1 = (const float*)d_in[2];
    const float* b1 = (const float*)d_in[3];
    const float* W2 = (const float*)d_in[4];
    const float* b2 = (const float*)d_in[5];
    float* out = (float*)d_out;

    int n = in_sizes[0] / FD;
    if (n > NMAX) n = NMAX;
    int E = in_sizes[1] / 2;
    if (E > EMAX) E = EMAX;

    float *bufA, *bufB;
    cudaGetSymbolAddress((void**)&bufA, d_bufA);
    cudaGetSymbolAddress((void**)&bufB, d_bufB);
    __half* gbuf = (__half*)bufA;

    cudaFuncSetAttribute(gemm_tc,
                         cudaFuncAttributeMaxDynamicSharedMemorySize, GEMM_SMEM);

    const int nblk_scan = (n + SCAN_C - 1) / SCAN_C;
    const int ntiles = (n + 63) / 64;
    const int ggrid = (ntiles < 2 * NSM) ? ntiles : 2 * NSM;

    // 1-3: degree + dinv + W1 split
    zero_deg_detect<<<(n + 255) / 256, 256>>>(ei, W1, n);
    deg_count<<<(E + 255) / 256, 256>>>(ei, E);
    finish_dinv<<<(n + 255) / 256, 256>>>(n);

    // 4 (ncu capture slot): layer-1 persistent HMMA GEMM -> g1 (fp16)
    gemm_tc<<<ggrid, 256, GEMM_SMEM>>>(x, gbuf, n, ntiles);

    // 5: split W2 into the W image buffers (gemm1 done with them)
    w_split<<<64, 256>>>(W2);

    // CSR build
    scan_partial<<<nblk_scan, SCAN_T>>>(n);
    scan_blocksums<<<1, 32>>>(nblk_scan);
    scan_add<<<(n + 255) / 256, 256>>>(n, E);
    scatter_csr<<<(E + 255) / 256, 256>>>(ei, E);

    // layer 1 aggregate (+relu): g1 fp16 -> h fp32
    aggregate_csr<<<(n + 7) / 8, 256>>>(gbuf, b1, bufB, n, 1);

    // layer 2: h -> g2 (fp16) -> out fp32
    gemm_tc<<<ggrid, 256, GEMM_SMEM>>>(bufB, gbuf, n, ntiles);
    aggregate_csr<<<(n + 7) / 8, 256>>>(gbuf, b2, out, n, 0);
}

// round 10
// speedup vs baseline: 12.1223x; 1.0091x over previous
#include <cuda_runtime.h>
#include <cuda_bf16.h>
#include <cuda_fp16.h>
#include <cstdint>

// GNN_9869834846215: two-layer cached GCN.
//   g = dinv ⊙ (h W)  -- persistent HMMA bf16x2-split GEMM, 2 blocks/SM
//   out[d] = dinv[d]*(Σ_{s∈N(d)} g[s] + g[d]) + b  -- CSR warp-per-node gather

#define NMAX 100000
#define EMAX 1700000
#define FD 128
#define SCAN_T 1024
#define SCAN_C 4096
#define SCAN_NBLK 25                      // ceil(100000/4096)
#define NSM 148

#define BSTRIDE 136                       // bf16 row stride (272B): ldmatrix conflict-free
#define T_SH (128 * BSTRIDE * 2)          // 34816 B (128-row bf16 tile: B images)
#define A_SH (64 * BSTRIDE * 2)           // 17408 B (64-row bf16 tile: A images)
#define GEMM_SMEM (2 * T_SH + 2 * A_SH)   // 104448 B -> 2 blocks/SM

// Scratch (__device__ globals per allocation-free rule)
__device__ float d_dinv[NMAX];
__device__ float d_bufA[(size_t)NMAX * FD];   // g (fp16, viewed as half*)
__device__ float d_bufB[(size_t)NMAX * FD];   // h (fp32)
__device__ int   d_degi[NMAX];
__device__ int   d_off[NMAX + 1];
__device__ int   d_cursor[NMAX];
__device__ int   d_csr[EMAX];
__device__ int   d_blocksums[32];
// W^T split into bf16 hi/lo, layout [n][k] with row stride BSTRIDE
__device__ __align__(16) unsigned short d_Whi[128 * BSTRIDE];
__device__ __align__(16) unsigned short d_Wlo[128 * BSTRIDE];

// ---------------------------------------------------------------------------
__device__ __forceinline__ uint32_t smem_u32(const void* p) {
    uint32_t a;
    asm("{ .reg .u64 t; cvta.to.shared.u64 t, %1; cvt.u32.u64 %0, t; }"
        : "=r"(a) : "l"(p));
    return a;
}

__device__ __forceinline__ void ldm_x4(uint32_t* r, uint32_t addr) {
    asm volatile("ldmatrix.sync.aligned.m8n8.x4.shared.b16 {%0,%1,%2,%3}, [%4];"
                 : "=r"(r[0]), "=r"(r[1]), "=r"(r[2]), "=r"(r[3]) : "r"(addr));
}

__device__ __forceinline__ void mma_bf16(float* c, const uint32_t* a,
                                         const uint32_t* b) {
    asm volatile(
        "mma.sync.aligned.m16n8k16.row.col.f32.bf16.bf16.f32 "
        "{%0,%1,%2,%3}, {%4,%5,%6,%7}, {%8,%9}, {%0,%1,%2,%3};"
        : "+f"(c[0]), "+f"(c[1]), "+f"(c[2]), "+f"(c[3])
        : "r"(a[0]), "r"(a[1]), "r"(a[2]), "r"(a[3]), "r"(b[0]), "r"(b[1]));
}

__device__ __forceinline__ unsigned short bfbits(__nv_bfloat16 h) {
    return __bfloat16_as_ushort(h);
}

// Block-local edge-dtype detection (int64 vs int32); node ids < 2^31 so
// int64 data has zero high words in the first 64 pairs.
__device__ __forceinline__ int detect64_local(const void* ei, int* s64) {
    if (threadIdx.x == 0) {
        const int2* p = (const int2*)ei;
        int is64 = 1;
        for (int j = 0; j < 64; ++j)
            if (p[j].y != 0) { is64 = 0; break; }
        *s64 = is64;
    }
    __syncthreads();
    return *s64;
}

// ---------------------------------------------------------------------------
// Split one W element into the hi/lo B images. B[n][k] = W[k][n].
__device__ __forceinline__ void w_split_elem(const float* W, int idx) {
    int nn = idx & 127, kk = idx >> 7;
    float v = W[kk * FD + nn];
    __nv_bfloat16 hi = __float2bfloat16_rn(v);
    __nv_bfloat16 lo = __float2bfloat16_rn(v - __bfloat162float(hi));
    d_Whi[nn * BSTRIDE + kk] = bfbits(hi);
    d_Wlo[nn * BSTRIDE + kk] = bfbits(lo);
}

__global__ void deg_count(const void* __restrict__ ei, int E) {
    __shared__ int s64;
    int is64 = detect64_local(ei, &s64);
    int i = blockIdx.x * blockDim.x + threadIdx.x;
    if (i >= E) return;
    int d = is64 ? (int)((const long long*)ei)[(size_t)E + i]
                 : ((const int*)ei)[(size_t)E + i];
    atomicAdd(&d_degi[d], 1);
}

// ---------------------------------------------------------------------------
// scan_partial: blocks [0,SCAN_NBLK) do the chunked exclusive degree scan and
// compute dinv; blocks [SCAN_NBLK, SCAN_NBLK+16) split W1 into bf16 images.
__global__ void __launch_bounds__(SCAN_T)
scan_partial(const float* __restrict__ W1, int n) {
    if (blockIdx.x >= SCAN_NBLK) {
        int idx = (blockIdx.x - SCAN_NBLK) * SCAN_T + threadIdx.x;
        if (idx < 16384) w_split_elem(W1, idx);
        return;
    }
    __shared__ int ssum[SCAN_T];
    const int tid  = threadIdx.x;
    const int base = blockIdx.x * SCAN_C + tid * 4;

    int v[4];
#pragma unroll
    for (int i = 0; i < 4; ++i) {
        v[i] = (base + i < n) ? d_degi[base + i] : 0;
        if (base + i < n) d_dinv[base + i] = rsqrtf((float)v[i] + 1.0f);
    }
    int tsum = v[0] + v[1] + v[2] + v[3];
    ssum[tid] = tsum;
    __syncthreads();
    for (int off = 1; off < SCAN_T; off <<= 1) {
        int t = (tid >= off) ? ssum[tid - off] : 0;
        __syncthreads();
        ssum[tid] += t;
        __syncthreads();
    }
    int texcl = ssum[tid] - tsum;
    if (tid == SCAN_T - 1) d_blocksums[blockIdx.x] = ssum[tid];

    int run = texcl;
#pragma unroll
    for (int i = 0; i < 4; ++i) {
        if (base + i < n) d_off[base + i] = run;
        run += v[i];
    }
}

__global__ void scan_blocksums(int nblk) {
    int tid = threadIdx.x;
    int v = (tid < nblk) ? d_blocksums[tid] : 0;
    int orig = v;
#pragma unroll
    for (int o = 1; o < 32; o <<= 1) {
        int t = __shfl_up_sync(0xFFFFFFFFu, v, o);
        if (tid >= o) v += t;
    }
    if (tid < nblk) d_blocksums[tid] = v - orig;
}

__global__ void scan_add(int n, int E) {
    int i = blockIdx.x * blockDim.x + threadIdx.x;
    if (i < n) {
        int v = d_off[i] + d_blocksums[i / SCAN_C];
        d_off[i] = v;
        d_cursor[i] = v;
    }
    if (i == 0) d_off[n] = E;
}

// scatter_csr + W2 split: scatter blocks [0,sblk), W2-split blocks [sblk,+64)
__global__ void scatter_ws(const void* __restrict__ ei, int E, int sblk,
                           const float* __restrict__ W2) {
    if (blockIdx.x >= sblk) {
        int idx = (blockIdx.x - sblk) * 256 + threadIdx.x;
        if (idx < 16384) w_split_elem(W2, idx);
        return;
    }
    __shared__ int s64;
    int is64 = detect64_local(ei, &s64);
    int i = blockIdx.x * blockDim.x + threadIdx.x;
    if (i >= E) return;
    int si, di;
    if (is64) {
        const long long* p = (const long long*)ei;
        si = (int)p[i];
        di = (int)p[(size_t)E + i];
    } else {
        const int* p = (const int*)ei;
        si = p[i];
        di = p[(size_t)E + i];
    }
    int pos = atomicAdd(&d_cursor[di], 1);
    d_csr[pos] = si;
}

// ---------------------------------------------------------------------------
// Persistent HMMA GEMM: gout[row] = fp16( dinv[row] * (in[row] @ W) ).
// 64-row tiles, 8 warps (warp tile 32x32), 2 blocks/SM (16 MMA warps/SM).
// Term-major MMA emission: same-acc HMMAs spaced 8 issues apart (breaks the
// 3-deep accumulator RAW chain of the acc-major order).
__global__ void __launch_bounds__(256, 2)
gemm_tc(const float* __restrict__ in, __half* __restrict__ gout,
        int n, int ntiles) {
    extern __shared__ char dsm[];
    char* sBh = dsm;
    char* sBl = dsm + T_SH;
    char* sAh = dsm + 2 * T_SH;
    char* sAl = dsm + 2 * T_SH + A_SH;

    const int tid = threadIdx.x;
    const int wid = tid >> 5;
    const int lid = tid & 31;

    // --- Stage B once: linear copy of pre-split global images ---
    {
        const float4* wh = (const float4*)d_Whi;
        const float4* wl = (const float4*)d_Wlo;
        float4* bh = (float4*)sBh;
        float4* bl = (float4*)sBl;
        for (int i = tid; i < T_SH / 16; i += 256) { bh[i] = wh[i]; bl[i] = wl[i]; }
    }

    // --- Warp tiling: warp tile 32 rows x 32 cols ---
    const int mrow0 = (wid >> 2) * 32;     // 0 or 32
    const int ncol0 = (wid & 3) * 32;      // 0,32,64,96
    const int sel   = lid >> 3;
    const int rowIn = lid & 7;
    const uint32_t aoff =
        (uint32_t)(((mrow0 + rowIn + (sel & 1) * 8) * BSTRIDE + (sel >> 1) * 8) * 2);
    const uint32_t boff =
        (uint32_t)(((ncol0 + (sel >> 1) * 8 + rowIn) * BSTRIDE + (sel & 1) * 8) * 2);
    const uint32_t aHi = smem_u32(sAh) + aoff;
    const uint32_t aLo = smem_u32(sAl) + aoff;
    const uint32_t bHi = smem_u32(sBh) + boff;
    const uint32_t bLo = smem_u32(sBl) + boff;

    // A staging: thread -> (row, col-quarter)
    const int ar = tid >> 2;           // 0..63
    const int ac = tid & 3;            // col quarter (32 cols)

    for (int t = blockIdx.x; t < ntiles; t += gridDim.x) {
        // --- Stage A tile: load fp32, split hi/lo bf16 ---
        {
            int gr = t * 64 + ar;
            if (gr >= n) gr = n - 1;
            const float4* src = (const float4*)(in + (size_t)gr * FD) + ac * 8;
            unsigned short* ah = (unsigned short*)sAh + ar * BSTRIDE + ac * 32;
            unsigned short* al = (unsigned short*)sAl + ar * BSTRIDE + ac * 32;
#pragma unroll
            for (int i = 0; i < 8; ++i) {
                float4 v = __ldg(src + i);
                __nv_bfloat16 h0 = __float2bfloat16_rn(v.x);
                __nv_bfloat16 h1 = __float2bfloat16_rn(v.y);
                __nv_bfloat16 h2 = __float2bfloat16_rn(v.z);
                __nv_bfloat16 h3 = __float2bfloat16_rn(v.w);
                *(uint32_t*)(ah + i * 4)     = (uint32_t)bfbits(h0) | ((uint32_t)bfbits(h1) << 16);
                *(uint32_t*)(ah + i * 4 + 2) = (uint32_t)bfbits(h2) | ((uint32_t)bfbits(h3) << 16);
                *(uint32_t*)(al + i * 4) =
                    (uint32_t)bfbits(__float2bfloat16_rn(v.x - __bfloat162float(h0))) |
                    ((uint32_t)bfbits(__float2bfloat16_rn(v.y - __bfloat162float(h1))) << 16);
                *(uint32_t*)(al + i * 4 + 2) =
                    (uint32_t)bfbits(__float2bfloat16_rn(v.z - __bfloat162float(h2))) |
                    ((uint32_t)bfbits(__float2bfloat16_rn(v.w - __bfloat162float(h3))) << 16);
            }
        }
        __syncthreads();

        // --- MMA phase ---
        float acc[2][4][4];
#pragma unroll
        for (int i = 0; i < 2; ++i)
#pragma unroll
            for (int j = 0; j < 4; ++j)
#pragma unroll
                for (int q = 0; q < 4; ++q) acc[i][j][q] = 0.f;

#pragma unroll
        for (int ks = 0; ks < 8; ++ks) {
            const uint32_t kb = ks * 32;
            uint32_t ah[2][4], al[2][4], bh2[4][2], bl2[4][2];
#pragma unroll
            for (int i = 0; i < 2; ++i) {
                ldm_x4(ah[i], aHi + i * (16 * BSTRIDE * 2) + kb);
                ldm_x4(al[i], aLo + i * (16 * BSTRIDE * 2) + kb);
            }
#pragma unroll
            for (int j2 = 0; j2 < 2; ++j2) {
                uint32_t q[4];
                ldm_x4(q, bHi + j2 * (16 * BSTRIDE * 2) + kb);
                bh2[2 * j2][0] = q[0]; bh2[2 * j2][1] = q[1];
                bh2[2 * j2 + 1][0] = q[2]; bh2[2 * j2 + 1][1] = q[3];
                ldm_x4(q, bLo + j2 * (16 * BSTRIDE * 2) + kb);
                bl2[2 * j2][0] = q[0]; bl2[2 * j2][1] = q[1];
                bl2[2 * j2 + 1][0] = q[2]; bl2[2 * j2 + 1][1] = q[3];
            }
            // term-major: 8 independent HMMAs per group; same acc revisited
            // only after 8 issues.
#pragma unroll
            for (int i = 0; i < 2; ++i)
#pragma unroll
                for (int j = 0; j < 4; ++j) mma_bf16(acc[i][j], ah[i], bh2[j]);
#pragma unroll
            for (int i = 0; i < 2; ++i)
#pragma unroll
                for (int j = 0; j < 4; ++j) mma_bf16(acc[i][j], ah[i], bl2[j]);
#pragma unroll
            for (int i = 0; i < 2; ++i)
#pragma unroll
                for (int j = 0; j < 4; ++j) mma_bf16(acc[i][j], al[i], bh2[j]);
        }

        // --- Epilogue: scale by dinv, convert fp16, store ---
        {
            const int rb = t * 64 + mrow0 + (lid >> 2);
            const int cbase = ncol0 + 2 * (lid & 3);
#pragma unroll
            for (int i = 0; i < 2; ++i) {
                int r1 = rb + 16 * i;
                int r2 = r1 + 8;
                float dv1 = (r1 < n) ? d_dinv[r1] : 0.f;
                float dv2 = (r2 < n) ? d_dinv[r2] : 0.f;
#pragma unroll
                for (int j = 0; j < 4; ++j) {
                    int c = cbase + 8 * j;
                    if (r1 < n)
                        *(__half2*)(gout + (size_t)r1 * FD + c) =
                            __floats2half2_rn(acc[i][j][0] * dv1, acc[i][j][1] * dv1);
                    if (r2 < n)
                        *(__half2*)(gout + (size_t)r2 * FD + c) =
                            __floats2half2_rn(acc[i][j][2] * dv2, acc[i][j][3] * dv2);
                }
            }
        }
        __syncthreads();
    }
}

// ---------------------------------------------------------------------------
// Fused aggregate + epilogue: one warp per dst node, fp16 gather, fp32 out.
__global__ void __launch_bounds__(256)
aggregate_csr(const __half* __restrict__ g, const float* __restrict__ bias,
              float* __restrict__ out, int n, int do_relu) {
    const int w = blockIdx.x * 8 + (threadIdx.x >> 5);
    if (w >= n) return;
    const int lane = threadIdx.x & 31;

    const uint2* gw = (const uint2*)g + lane;   // row stride: 32 uint2

    float acc0, acc1, acc2, acc3;
    {
        uint2 raw = __ldg(gw + (size_t)w * 32);  // self-loop term
        float2 f0 = __half22float2(*(__half2*)&raw.x);
        float2 f1 = __half22float2(*(__half2*)&raw.y);
        acc0 = f0.x; acc1 = f0.y; acc2 = f1.x; acc3 = f1.y;
    }

    int e = d_off[w];
    const int eend = d_off[w + 1];
    for (; e + 4 <= eend; e += 4) {
        int s0 = __ldg(&d_csr[e]);
        int s1 = __ldg(&d_csr[e + 1]);
        int s2 = __ldg(&d_csr[e + 2]);
        int s3 = __ldg(&d_csr[e + 3]);
        uint2 ra = __ldg(gw + (size_t)s0 * 32);
        uint2 rb = __ldg(gw + (size_t)s1 * 32);
        uint2 rc = __ldg(gw + (size_t)s2 * 32);
        uint2 rd = __ldg(gw + (size_t)s3 * 32);
        float2 a0 = __half22float2(*(__half2*)&ra.x), a1 = __half22float2(*(__half2*)&ra.y);
        float2 b0 = __half22float2(*(__half2*)&rb.x), b1 = __half22float2(*(__half2*)&rb.y);
        float2 c0 = __half22float2(*(__half2*)&rc.x), c1 = __half22float2(*(__half2*)&rc.y);
        float2 d0 = __half22float2(*(__half2*)&rd.x), d1 = __half22float2(*(__half2*)&rd.y);
        acc0 += (a0.x + b0.x) + (c0.x + d0.x);
        acc1 += (a0.y + b0.y) + (c0.y + d0.y);
        acc2 += (a1.x + b1.x) + (c1.x + d1.x);
        acc3 += (a1.y + b1.y) + (c1.y + d1.y);
    }
    for (; e < eend; ++e) {
        int s0 = __ldg(&d_csr[e]);
        uint2 ra = __ldg(gw + (size_t)s0 * 32);
        float2 a0 = __half22float2(*(__half2*)&ra.x), a1 = __half22float2(*(__half2*)&ra.y);
        acc0 += a0.x; acc1 += a0.y; acc2 += a1.x; acc3 += a1.y;
    }

    const float dv = d_dinv[w];
    float4 bs = __ldg((const float4*)bias + lane);
    float4 r;
    r.x = dv * acc0 + bs.x;
    r.y = dv * acc1 + bs.y;
    r.z = dv * acc2 + bs.z;
    r.w = dv * acc3 + bs.w;
    if (do_relu) {
        r.x = fmaxf(r.x, 0.f); r.y = fmaxf(r.y, 0.f);
        r.z = fmaxf(r.z, 0.f); r.w = fmaxf(r.w, 0.f);
    }
    ((float4*)(out + (size_t)w * FD))[lane] = r;
}

// ---------------------------------------------------------------------------
extern "C" void kernel_launch(void* const* d_in, const int* in_sizes, int n_in,
                              void* d_out, int out_size) {
    const float* x  = (const float*)d_in[0];
    const void*  ei = d_in[1];
    const float* W1 = (const float*)d_in[2];
    const float* b1 = (const float*)d_in[3];
    const float* W2 = (const float*)d_in[4];
    const float* b2 = (const float*)d_in[5];
    float* out = (float*)d_out;

    int n = in_sizes[0] / FD;
    if (n > NMAX) n = NMAX;
    int E = in_sizes[1] / 2;
    if (E > EMAX) E = EMAX;

    float *bufA, *bufB;
    int* degi;
    cudaGetSymbolAddress((void**)&bufA, d_bufA);
    cudaGetSymbolAddress((void**)&bufB, d_bufB);
    cudaGetSymbolAddress((void**)&degi, d_degi);
    __half* gbuf = (__half*)bufA;

    cudaFuncSetAttribute(gemm_tc,
                         cudaFuncAttributeMaxDynamicSharedMemorySize, GEMM_SMEM);

    const int ntiles = (n + 63) / 64;
    const int ggrid = (ntiles < 2 * NSM) ? ntiles : 2 * NSM;
    const int sblk = (E + 255) / 256;

    // CSR build front half + dinv + W1 split
    cudaMemsetAsync(degi, 0, (size_t)n * sizeof(int));
    deg_count<<<(E + 255) / 256, 256>>>(ei, E);
    scan_partial<<<SCAN_NBLK + 16, SCAN_T>>>(W1, n);
    scan_blocksums<<<1, 32>>>(SCAN_NBLK);
    scan_add<<<(n + 255) / 256, 256>>>(n, E);

    // layer-1 persistent HMMA GEMM -> g1 (fp16)
    gemm_tc<<<ggrid, 256, GEMM_SMEM>>>(x, gbuf, n, ntiles);

    // CSR scatter + W2 split (independent of gemm1 output)
    scatter_ws<<<sblk + 64, 256>>>(ei, E, sblk, W2);

    // layer 1 aggregate (+relu): g1 fp16 -> h fp32
    aggregate_csr<<<(n + 7) / 8, 256>>>(gbuf, b1, bufB, n, 1);

    // layer 2: h -> g2 (fp16) -> out fp32
    gemm_tc<<<ggrid, 256, GEMM_SMEM>>>(bufB, gbuf, n, ntiles);
    aggregate_csr<<<(n + 7) / 8, 256>>>(gbuf, b2, out, n, 0);
}